// round 5
// baseline (speedup 1.0000x reference)
#include <cuda_runtime.h>
#include <cuda_bf16.h>
#include <stdint.h>
#include <math.h>

#define H 1024
#define F 4096
#define E 8
#define TK 2
#define T 8192

#define BM 128
#define BN 64
#define BK 32
#define APITCH 40
#define BPITCH 72

// ---- device scratch (static: no allocations allowed) ----
__device__ int   g_cnt[E];
__device__ int   g_idx[E][T];
__device__ float g_cw[E][T];
__device__ float g_sumprob[E];
__device__ float g_zsum;
__device__ float g_h[(size_t)T * F];   // 128 MB intermediate, reused per expert

// ---------------------------------------------------------------------------
// tensor-core helpers
__device__ __forceinline__ unsigned sptr(const void* p) {
    return (unsigned)__cvta_generic_to_shared(p);
}
__device__ __forceinline__ void ldsm4(unsigned* r, unsigned a) {
    asm volatile("ldmatrix.sync.aligned.m8n8.x4.shared.b16 {%0,%1,%2,%3}, [%4];"
                 : "=r"(r[0]), "=r"(r[1]), "=r"(r[2]), "=r"(r[3]) : "r"(a));
}
__device__ __forceinline__ void ldsm4t(unsigned* r, unsigned a) {
    asm volatile("ldmatrix.sync.aligned.m8n8.x4.trans.shared.b16 {%0,%1,%2,%3}, [%4];"
                 : "=r"(r[0]), "=r"(r[1]), "=r"(r[2]), "=r"(r[3]) : "r"(a));
}
__device__ __forceinline__ void mma16816(float* d, const unsigned* a, const unsigned* b) {
    asm volatile("mma.sync.aligned.m16n8k16.row.col.f32.bf16.bf16.f32 "
                 "{%0,%1,%2,%3},{%4,%5,%6,%7},{%8,%9},{%0,%1,%2,%3};"
                 : "+f"(d[0]), "+f"(d[1]), "+f"(d[2]), "+f"(d[3])
                 : "r"(a[0]), "r"(a[1]), "r"(a[2]), "r"(a[3]), "r"(b[0]), "r"(b[1]));
}
// split two fp32 into packed bf16x2 (hi) and bf16x2 (lo residual)
__device__ __forceinline__ void split2(float x, float y, unsigned& hi, unsigned& lo) {
    __nv_bfloat16 hx = __float2bfloat16(x);
    __nv_bfloat16 hy = __float2bfloat16(y);
    __nv_bfloat16 lx = __float2bfloat16(x - __bfloat162float(hx));
    __nv_bfloat16 ly = __float2bfloat16(y - __bfloat162float(hy));
    __nv_bfloat162 h = __halves2bfloat162(hx, hy);
    __nv_bfloat162 l = __halves2bfloat162(lx, ly);
    hi = *reinterpret_cast<unsigned*>(&h);
    lo = *reinterpret_cast<unsigned*>(&l);
}

// ---- stage helpers (plain device functions; NO lambdas) ---------------------
// A tile: BM x BK floats, 256 threads x float4 x 4 iters. row = idx/8, q = idx%8.
__device__ __forceinline__ void ldA_gather(const float* __restrict__ src, size_t ld,
                                           const int* __restrict__ ridx,
                                           int k0, int tid, float4* pa) {
#pragma unroll
    for (int i = 0; i < 4; i++) {
        int idx = tid + i * 256; int r = idx >> 3; int q = idx & 7;
        int gr = ridx[r];
        pa[i] = (gr >= 0) ? *reinterpret_cast<const float4*>(src + (size_t)gr * ld + k0 + q * 4)
                          : make_float4(0.f, 0.f, 0.f, 0.f);
    }
}
__device__ __forceinline__ void ldA_linear(const float* __restrict__ src, size_t ld,
                                           int row0, int cnt,
                                           int k0, int tid, float4* pa) {
#pragma unroll
    for (int i = 0; i < 4; i++) {
        int idx = tid + i * 256; int r = idx >> 3; int q = idx & 7;
        int gr = row0 + r;
        pa[i] = (gr < cnt) ? *reinterpret_cast<const float4*>(src + (size_t)gr * ld + k0 + q * 4)
                           : make_float4(0.f, 0.f, 0.f, 0.f);
    }
}
__device__ __forceinline__ void stA(const float4* pa, int tid,
                                    __nv_bfloat16 (*Ahi)[APITCH],
                                    __nv_bfloat16 (*Alo)[APITCH]) {
#pragma unroll
    for (int i = 0; i < 4; i++) {
        int idx = tid + i * 256; int r = idx >> 3; int q = idx & 7;
        unsigned h0, h1, l0, l1;
        split2(pa[i].x, pa[i].y, h0, l0);
        split2(pa[i].z, pa[i].w, h1, l1);
        *reinterpret_cast<unsigned*>(&Ahi[r][q * 4])     = h0;
        *reinterpret_cast<unsigned*>(&Ahi[r][q * 4 + 2]) = h1;
        *reinterpret_cast<unsigned*>(&Alo[r][q * 4])     = l0;
        *reinterpret_cast<unsigned*>(&Alo[r][q * 4 + 2]) = l1;
    }
}
// B tile: BK x BN floats, 256 threads x float4 x 2 iters. row = idx/16, q = idx%16.
__device__ __forceinline__ void ldB(const float* __restrict__ src, size_t ld,
                                    int col0, int k0, int tid, float4* pb) {
#pragma unroll
    for (int i = 0; i < 2; i++) {
        int idx = tid + i * 256; int r = idx >> 4; int q = idx & 15;
        pb[i] = *reinterpret_cast<const float4*>(src + (size_t)(k0 + r) * ld + col0 + q * 4);
    }
}
__device__ __forceinline__ void stB(const float4* pb, int tid,
                                    __nv_bfloat16 (*Bhi)[BPITCH],
                                    __nv_bfloat16 (*Blo)[BPITCH]) {
#pragma unroll
    for (int i = 0; i < 2; i++) {
        int idx = tid + i * 256; int r = idx >> 4; int q = idx & 15;
        unsigned h0, h1, l0, l1;
        split2(pb[i].x, pb[i].y, h0, l0);
        split2(pb[i].z, pb[i].w, h1, l1);
        *reinterpret_cast<unsigned*>(&Bhi[r][q * 4])     = h0;
        *reinterpret_cast<unsigned*>(&Bhi[r][q * 4 + 2]) = h1;
        *reinterpret_cast<unsigned*>(&Blo[r][q * 4])     = l0;
        *reinterpret_cast<unsigned*>(&Blo[r][q * 4 + 2]) = l1;
    }
}

// ---------------------------------------------------------------------------
__global__ void zero_kernel(float* __restrict__ out) {
    size_t n = (size_t)T * H;
    size_t stride = (size_t)gridDim.x * blockDim.x;
    for (size_t i = (size_t)blockIdx.x * blockDim.x + threadIdx.x; i < n; i += stride)
        out[i] = 0.f;
    if (blockIdx.x == 0 && threadIdx.x < E) {
        g_cnt[threadIdx.x] = 0;
        g_sumprob[threadIdx.x] = 0.f;
    }
    if (blockIdx.x == 0 && threadIdx.x == E) g_zsum = 0.f;
}

// ---------------------------------------------------------------------------
// One warp per token: logits -> softmax -> top-2 -> gather lists + aux losses.
__global__ void router_kernel(const float* __restrict__ x,
                              const float* __restrict__ gw) {
    int warp = threadIdx.x >> 5;
    int lane = threadIdx.x & 31;
    int t = blockIdx.x * (blockDim.x >> 5) + warp;
    if (t >= T) return;

    const float* xr = x + (size_t)t * H;
    float acc[E];
#pragma unroll
    for (int e = 0; e < E; e++) acc[e] = 0.f;

    for (int h = lane; h < H; h += 32) {
        float xv = xr[h];
#pragma unroll
        for (int e = 0; e < E; e++) acc[e] += xv * gw[h * E + e];
    }
#pragma unroll
    for (int off = 16; off; off >>= 1) {
#pragma unroll
        for (int e = 0; e < E; e++)
            acc[e] += __shfl_down_sync(0xffffffffu, acc[e], off);
    }

    if (lane == 0) {
        float m = acc[0];
#pragma unroll
        for (int e = 1; e < E; e++) m = fmaxf(m, acc[e]);
        float p[E], s = 0.f;
#pragma unroll
        for (int e = 0; e < E; e++) { p[e] = __expf(acc[e] - m); s += p[e]; }
        float inv = 1.f / s;
        float lse = m + logf(s);
        atomicAdd(&g_zsum, lse * lse);

        int i1 = 0; float p1 = -1.f;
#pragma unroll
        for (int e = 0; e < E; e++) {
            float pe = p[e] * inv;
            p[e] = pe;
            atomicAdd(&g_sumprob[e], pe);
            if (pe > p1) { p1 = pe; i1 = e; }   // first index wins ties (matches jax)
        }
        int i2 = -1; float p2 = -1.f;
#pragma unroll
        for (int e = 0; e < E; e++) {
            if (e != i1 && p[e] > p2) { p2 = p[e]; i2 = e; }
        }
        float rs = 1.f / (p1 + p2);
        float w1 = p1 * rs, w2 = p2 * rs;

        int pos1 = atomicAdd(&g_cnt[i1], 1);
        g_idx[i1][pos1] = t; g_cw[i1][pos1] = w1;
        int pos2 = atomicAdd(&g_cnt[i2], 1);
        g_idx[i2][pos2] = t; g_cw[i2][pos2] = w2;
    }
}

// ---------------------------------------------------------------------------
// GEMM1 (tensor cores): h = silu(x_g @ Wg) * (x_g @ Wu), gathered rows.
// 128x64x32 tile, 8 warps (4m x 2n), warp tile 32x32, bf16 hi/lo 3-pass fp32 emu.
__global__ __launch_bounds__(256, 1) void gemm1_tc(
    const float* __restrict__ x, const float* __restrict__ Wg,
    const float* __restrict__ Wu, int e)
{
    int cnt = g_cnt[e];
    int row0 = blockIdx.y * BM;
    if (row0 >= cnt) return;
    int col0 = blockIdx.x * BN;

    __shared__ __nv_bfloat16 Ahi[BM][APITCH], Alo[BM][APITCH];
    __shared__ __nv_bfloat16 Bhi[2][BK][BPITCH], Blo[2][BK][BPITCH]; // [0]=gate,[1]=up
    __shared__ int ridx[BM];

    int tid = threadIdx.x;
    int lane = tid & 31, wid = tid >> 5;
    int wm = (wid & 3) * 32, wn = (wid >> 2) * 32;

    if (tid < BM) { int r = row0 + tid; ridx[tid] = (r < cnt) ? g_idx[e][r] : -1; }
    __syncthreads();

    float acc[2][2][4][4]; // [gate/up][mi][nj][frag]
#pragma unroll
    for (int a = 0; a < 2; a++)
#pragma unroll
        for (int b = 0; b < 2; b++)
#pragma unroll
            for (int c = 0; c < 4; c++)
#pragma unroll
                for (int d = 0; d < 4; d++) acc[a][b][c][d] = 0.f;

    float4 pa[4], pbg[2], pbu[2];

    const int NK = H / BK;
    ldA_gather(x, H, ridx, 0, tid, pa);
    ldB(Wg, F, col0, 0, tid, pbg);
    ldB(Wu, F, col0, 0, tid, pbu);
    stA(pa, tid, Ahi, Alo);
    stB(pbg, tid, Bhi[0], Blo[0]);
    stB(pbu, tid, Bhi[1], Blo[1]);
    __syncthreads();

    for (int kt = 0; kt < NK; kt++) {
        if (kt + 1 < NK) {
            ldA_gather(x, H, ridx, (kt + 1) * BK, tid, pa);
            ldB(Wg, F, col0, (kt + 1) * BK, tid, pbg);
            ldB(Wu, F, col0, (kt + 1) * BK, tid, pbu);
        }
#pragma unroll
        for (int ks = 0; ks < 2; ks++) {
            unsigned ah[2][4], al[2][4];
            int ar = wm + (lane & 15), ac = ks * 16 + (lane >> 4) * 8;
#pragma unroll
            for (int mi = 0; mi < 2; mi++) {
                ldsm4(ah[mi], sptr(&Ahi[ar + mi * 16][ac]));
                ldsm4(al[mi], sptr(&Alo[ar + mi * 16][ac]));
            }
            int br = ks * 16 + (lane & 15), bc = wn + (lane >> 4) * 8;
#pragma unroll
            for (int mat = 0; mat < 2; mat++) {
                unsigned bh[2][4], bl[2][4];
#pragma unroll
                for (int nh = 0; nh < 2; nh++) {
                    ldsm4t(bh[nh], sptr(&Bhi[mat][br][bc + nh * 16]));
                    ldsm4t(bl[nh], sptr(&Blo[mat][br][bc + nh * 16]));
                }
#pragma unroll
                for (int mi = 0; mi < 2; mi++)
#pragma unroll
                    for (int nh = 0; nh < 2; nh++)
#pragma unroll
                        for (int s = 0; s < 2; s++) {
                            int nj = nh * 2 + s;
                            mma16816(acc[mat][mi][nj], ah[mi], &bh[nh][s * 2]);
                            mma16816(acc[mat][mi][nj], ah[mi], &bl[nh][s * 2]);
                            mma16816(acc[mat][mi][nj], al[mi], &bh[nh][s * 2]);
                        }
            }
        }
        __syncthreads();
        if (kt + 1 < NK) {
            stA(pa, tid, Ahi, Alo);
            stB(pbg, tid, Bhi[0], Blo[0]);
            stB(pbu, tid, Bhi[1], Blo[1]);
            __syncthreads();
        }
    }

    // epilogue: silu(g)*u -> g_h
#pragma unroll
    for (int mi = 0; mi < 2; mi++)
#pragma unroll
        for (int half = 0; half < 2; half++) {
            int m = wm + mi * 16 + (lane >> 2) + half * 8;
            int r = row0 + m;
            if (r < cnt) {
                float* dst = g_h + (size_t)r * F + col0 + wn + (lane & 3) * 2;
#pragma unroll
                for (int nj = 0; nj < 4; nj++) {
                    float g0 = acc[0][mi][nj][half * 2 + 0];
                    float g1 = acc[0][mi][nj][half * 2 + 1];
                    float u0 = acc[1][mi][nj][half * 2 + 0];
                    float u1 = acc[1][mi][nj][half * 2 + 1];
                    float h0 = g0 / (1.f + __expf(-g0)) * u0;
                    float h1 = g1 / (1.f + __expf(-g1)) * u1;
                    *reinterpret_cast<float2*>(dst + nj * 8) = make_float2(h0, h1);
                }
            }
        }
}

// ---------------------------------------------------------------------------
// GEMM2 (tensor cores): out[tok,:] += w * (h[r,:] @ Wd). Scatter epilogue.
__global__ __launch_bounds__(256, 1) void gemm2_tc(
    const float* __restrict__ Wd, float* __restrict__ out, int e)
{
    int cnt = g_cnt[e];
    int row0 = blockIdx.y * BM;
    if (row0 >= cnt) return;
    int col0 = blockIdx.x * BN;

    __shared__ __nv_bfloat16 Ahi[BM][APITCH], Alo[BM][APITCH];
    __shared__ __nv_bfloat16 Bhi[BK][BPITCH], Blo[BK][BPITCH];

    int tid = threadIdx.x;
    int lane = tid & 31, wid = tid >> 5;
    int wm = (wid & 3) * 32, wn = (wid >> 2) * 32;

    float acc[2][4][4];
#pragma unroll
    for (int b = 0; b < 2; b++)
#pragma unroll
        for (int c = 0; c < 4; c++)
#pragma unroll
            for (int d = 0; d < 4; d++) acc[b][c][d] = 0.f;

    float4 pa[4], pb[2];

    const int NK = F / BK;
    ldA_linear(g_h, F, row0, cnt, 0, tid, pa);
    ldB(Wd, H, col0, 0, tid, pb);
    stA(pa, tid, Ahi, Alo);
    stB(pb, tid, Bhi, Blo);
    __syncthreads();

    for (int kt = 0; kt < NK; kt++) {
        if (kt + 1 < NK) {
            ldA_linear(g_h, F, row0, cnt, (kt + 1) * BK, tid, pa);
            ldB(Wd, H, col0, (kt + 1) * BK, tid, pb);
        }
#pragma unroll
        for (int ks = 0; ks < 2; ks++) {
            unsigned ah[2][4], al[2][4];
            int ar = wm + (lane & 15), ac = ks * 16 + (lane >> 4) * 8;
#pragma unroll
            for (int mi = 0; mi < 2; mi++) {
                ldsm4(ah[mi], sptr(&Ahi[ar + mi * 16][ac]));
                ldsm4(al[mi], sptr(&Alo[ar + mi * 16][ac]));
            }
            int br = ks * 16 + (lane & 15), bc = wn + (lane >> 4) * 8;
            unsigned bh[2][4], bl[2][4];
#pragma unroll
            for (int nh = 0; nh < 2; nh++) {
                ldsm4t(bh[nh], sptr(&Bhi[br][bc + nh * 16]));
                ldsm4t(bl[nh], sptr(&Blo[br][bc + nh * 16]));
            }
#pragma unroll
            for (int mi = 0; mi < 2; mi++)
#pragma unroll
                for (int nh = 0; nh < 2; nh++)
#pragma unroll
                    for (int s = 0; s < 2; s++) {
                        int nj = nh * 2 + s;
                        mma16816(acc[mi][nj], ah[mi], &bh[nh][s * 2]);
                        mma16816(acc[mi][nj], ah[mi], &bl[nh][s * 2]);
                        mma16816(acc[mi][nj], al[mi], &bh[nh][s * 2]);
                    }
        }
        __syncthreads();
        if (kt + 1 < NK) {
            stA(pa, tid, Ahi, Alo);
            stB(pb, tid, Bhi, Blo);
            __syncthreads();
        }
    }

    // epilogue: scatter-accumulate into out (experts serialized by stream order)
#pragma unroll
    for (int mi = 0; mi < 2; mi++)
#pragma unroll
        for (int half = 0; half < 2; half++) {
            int m = wm + mi * 16 + (lane >> 2) + half * 8;
            int r = row0 + m;
            if (r < cnt) {
                int tok = g_idx[e][r];
                float w = g_cw[e][r];
                float* o = out + (size_t)tok * H + col0 + wn + (lane & 3) * 2;
#pragma unroll
                for (int nj = 0; nj < 4; nj++) {
                    o[nj * 8 + 0] += w * acc[mi][nj][half * 2 + 0];
                    o[nj * 8 + 1] += w * acc[mi][nj][half * 2 + 1];
                }
            }
        }
}

// ---------------------------------------------------------------------------
__global__ void finalize_kernel(float* __restrict__ out, int out_size) {
    if (threadIdx.x == 0 && blockIdx.x == 0) {
        float bal = 0.f;
#pragma unroll
        for (int e = 0; e < E; e++)
            bal += ((float)g_cnt[e] / (float)(T * TK)) * (g_sumprob[e] / (float)T);
        out[out_size - 2] = (float)E * bal;
        out[out_size - 1] = g_zsum / (float)T;
    }
}

// ---------------------------------------------------------------------------
extern "C" void kernel_launch(void* const* d_in, const int* in_sizes, int n_in,
                              void* d_out, int out_size) {
    const float* x  = (const float*)d_in[0];   // [4,2048,1024]
    const float* gw = (const float*)d_in[1];   // [1024,8]
    const float* wg = (const float*)d_in[2];   // [8,1024,4096]
    const float* wu = (const float*)d_in[3];   // [8,1024,4096]
    const float* wd = (const float*)d_in[4];   // [8,4096,1024]
    float* out = (float*)d_out;

    zero_kernel<<<512, 256>>>(out);
    router_kernel<<<T / 8, 256>>>(x, gw);

    dim3 g1(F / BN, (T + BM - 1) / BM);   // 64 x 64
    dim3 g2(H / BN, (T + BM - 1) / BM);   // 16 x 64
    for (int e = 0; e < E; e++) {
        gemm1_tc<<<g1, 256>>>(x, wg + (size_t)e * H * F, wu + (size_t)e * H * F, e);
        gemm2_tc<<<g2, 256>>>(wd + (size_t)e * F * H, out, e);
    }

    finalize_kernel<<<1, 32>>>(out, out_size);
}

// round 6
// speedup vs baseline: 1.0003x; 1.0003x over previous
#include <cuda_runtime.h>
#include <cuda_bf16.h>
#include <stdint.h>
#include <math.h>

#define H 1024
#define F 4096
#define E 8
#define TK 2
#define T 8192

#define BM 128
#define BN 64
#define BK 32
#define APITCH 40
#define BPITCH 72

// ---- device scratch (static: no allocations allowed) ----
__device__ int   g_cnt[E];
__device__ int   g_idx[E][T];
__device__ float g_cw[E][T];
__device__ float g_sumprob[E];
__device__ float g_zsum;
__device__ float g_h[(size_t)T * F];   // 128 MB intermediate, reused per expert

// ---------------------------------------------------------------------------
// tensor-core helpers
__device__ __forceinline__ unsigned sptr(const void* p) {
    return (unsigned)__cvta_generic_to_shared(p);
}
__device__ __forceinline__ void ldsm4(unsigned* r, unsigned a) {
    asm volatile("ldmatrix.sync.aligned.m8n8.x4.shared.b16 {%0,%1,%2,%3}, [%4];"
                 : "=r"(r[0]), "=r"(r[1]), "=r"(r[2]), "=r"(r[3]) : "r"(a));
}
__device__ __forceinline__ void ldsm4t(unsigned* r, unsigned a) {
    asm volatile("ldmatrix.sync.aligned.m8n8.x4.trans.shared.b16 {%0,%1,%2,%3}, [%4];"
                 : "=r"(r[0]), "=r"(r[1]), "=r"(r[2]), "=r"(r[3]) : "r"(a));
}
__device__ __forceinline__ void mma16816(float* d, const unsigned* a, const unsigned* b) {
    asm volatile("mma.sync.aligned.m16n8k16.row.col.f32.bf16.bf16.f32 "
                 "{%0,%1,%2,%3},{%4,%5,%6,%7},{%8,%9},{%0,%1,%2,%3};"
                 : "+f"(d[0]), "+f"(d[1]), "+f"(d[2]), "+f"(d[3])
                 : "r"(a[0]), "r"(a[1]), "r"(a[2]), "r"(a[3]), "r"(b[0]), "r"(b[1]));
}
// split two fp32 into packed bf16x2 (hi) and bf16x2 (lo residual)
__device__ __forceinline__ void split2(float x, float y, unsigned& hi, unsigned& lo) {
    __nv_bfloat16 hx = __float2bfloat16(x);
    __nv_bfloat16 hy = __float2bfloat16(y);
    __nv_bfloat16 lx = __float2bfloat16(x - __bfloat162float(hx));
    __nv_bfloat16 ly = __float2bfloat16(y - __bfloat162float(hy));
    __nv_bfloat162 h = __halves2bfloat162(hx, hy);
    __nv_bfloat162 l = __halves2bfloat162(lx, ly);
    hi = *reinterpret_cast<unsigned*>(&h);
    lo = *reinterpret_cast<unsigned*>(&l);
}

// ---- stage helpers (plain device functions; NO lambdas) ---------------------
// A tile: BM x BK floats, 256 threads x float4 x 4 iters. row = idx/8, q = idx%8.
__device__ __forceinline__ void ldA_gather(const float* __restrict__ src, size_t ld,
                                           const int* __restrict__ ridx,
                                           int k0, int tid, float4* pa) {
#pragma unroll
    for (int i = 0; i < 4; i++) {
        int idx = tid + i * 256; int r = idx >> 3; int q = idx & 7;
        int gr = ridx[r];
        pa[i] = (gr >= 0) ? *reinterpret_cast<const float4*>(src + (size_t)gr * ld + k0 + q * 4)
                          : make_float4(0.f, 0.f, 0.f, 0.f);
    }
}
__device__ __forceinline__ void ldA_linear(const float* __restrict__ src, size_t ld,
                                           int row0, int cnt,
                                           int k0, int tid, float4* pa) {
#pragma unroll
    for (int i = 0; i < 4; i++) {
        int idx = tid + i * 256; int r = idx >> 3; int q = idx & 7;
        int gr = row0 + r;
        pa[i] = (gr < cnt) ? *reinterpret_cast<const float4*>(src + (size_t)gr * ld + k0 + q * 4)
                           : make_float4(0.f, 0.f, 0.f, 0.f);
    }
}
__device__ __forceinline__ void stA(const float4* pa, int tid,
                                    __nv_bfloat16 (*Ahi)[APITCH],
                                    __nv_bfloat16 (*Alo)[APITCH]) {
#pragma unroll
    for (int i = 0; i < 4; i++) {
        int idx = tid + i * 256; int r = idx >> 3; int q = idx & 7;
        unsigned h0, h1, l0, l1;
        split2(pa[i].x, pa[i].y, h0, l0);
        split2(pa[i].z, pa[i].w, h1, l1);
        *reinterpret_cast<unsigned*>(&Ahi[r][q * 4])     = h0;
        *reinterpret_cast<unsigned*>(&Ahi[r][q * 4 + 2]) = h1;
        *reinterpret_cast<unsigned*>(&Alo[r][q * 4])     = l0;
        *reinterpret_cast<unsigned*>(&Alo[r][q * 4 + 2]) = l1;
    }
}
// B tile: BK x BN floats, 256 threads x float4 x 2 iters. row = idx/16, q = idx%16.
__device__ __forceinline__ void ldB(const float* __restrict__ src, size_t ld,
                                    int col0, int k0, int tid, float4* pb) {
#pragma unroll
    for (int i = 0; i < 2; i++) {
        int idx = tid + i * 256; int r = idx >> 4; int q = idx & 15;
        pb[i] = *reinterpret_cast<const float4*>(src + (size_t)(k0 + r) * ld + col0 + q * 4);
    }
}
__device__ __forceinline__ void stB(const float4* pb, int tid,
                                    __nv_bfloat16 (*Bhi)[BPITCH],
                                    __nv_bfloat16 (*Blo)[BPITCH]) {
#pragma unroll
    for (int i = 0; i < 2; i++) {
        int idx = tid + i * 256; int r = idx >> 4; int q = idx & 15;
        unsigned h0, h1, l0, l1;
        split2(pb[i].x, pb[i].y, h0, l0);
        split2(pb[i].z, pb[i].w, h1, l1);
        *reinterpret_cast<unsigned*>(&Bhi[r][q * 4])     = h0;
        *reinterpret_cast<unsigned*>(&Bhi[r][q * 4 + 2]) = h1;
        *reinterpret_cast<unsigned*>(&Blo[r][q * 4])     = l0;
        *reinterpret_cast<unsigned*>(&Blo[r][q * 4 + 2]) = l1;
    }
}

// ---------------------------------------------------------------------------
__global__ void zero_kernel(float* __restrict__ out) {
    size_t n = (size_t)T * H;
    size_t stride = (size_t)gridDim.x * blockDim.x;
    for (size_t i = (size_t)blockIdx.x * blockDim.x + threadIdx.x; i < n; i += stride)
        out[i] = 0.f;
    if (blockIdx.x == 0 && threadIdx.x < E) {
        g_cnt[threadIdx.x] = 0;
        g_sumprob[threadIdx.x] = 0.f;
    }
    if (blockIdx.x == 0 && threadIdx.x == E) g_zsum = 0.f;
}

// ---------------------------------------------------------------------------
// One warp per token: logits -> softmax -> top-2 -> gather lists + aux losses.
__global__ void router_kernel(const float* __restrict__ x,
                              const float* __restrict__ gw) {
    int warp = threadIdx.x >> 5;
    int lane = threadIdx.x & 31;
    int t = blockIdx.x * (blockDim.x >> 5) + warp;
    if (t >= T) return;

    const float* xr = x + (size_t)t * H;
    float acc[E];
#pragma unroll
    for (int e = 0; e < E; e++) acc[e] = 0.f;

    for (int h = lane; h < H; h += 32) {
        float xv = xr[h];
#pragma unroll
        for (int e = 0; e < E; e++) acc[e] += xv * gw[h * E + e];
    }
#pragma unroll
    for (int off = 16; off; off >>= 1) {
#pragma unroll
        for (int e = 0; e < E; e++)
            acc[e] += __shfl_down_sync(0xffffffffu, acc[e], off);
    }

    if (lane == 0) {
        float m = acc[0];
#pragma unroll
        for (int e = 1; e < E; e++) m = fmaxf(m, acc[e]);
        float p[E], s = 0.f;
#pragma unroll
        for (int e = 0; e < E; e++) { p[e] = __expf(acc[e] - m); s += p[e]; }
        float inv = 1.f / s;
        float lse = m + logf(s);
        atomicAdd(&g_zsum, lse * lse);

        int i1 = 0; float p1 = -1.f;
#pragma unroll
        for (int e = 0; e < E; e++) {
            float pe = p[e] * inv;
            p[e] = pe;
            atomicAdd(&g_sumprob[e], pe);
            if (pe > p1) { p1 = pe; i1 = e; }   // first index wins ties (matches jax)
        }
        int i2 = -1; float p2 = -1.f;
#pragma unroll
        for (int e = 0; e < E; e++) {
            if (e != i1 && p[e] > p2) { p2 = p[e]; i2 = e; }
        }
        float rs = 1.f / (p1 + p2);
        float w1 = p1 * rs, w2 = p2 * rs;

        int pos1 = atomicAdd(&g_cnt[i1], 1);
        g_idx[i1][pos1] = t; g_cw[i1][pos1] = w1;
        int pos2 = atomicAdd(&g_cnt[i2], 1);
        g_idx[i2][pos2] = t; g_cw[i2][pos2] = w2;
    }
}

// ---------------------------------------------------------------------------
// GEMM1 (tensor cores): h = silu(x_g @ Wg) * (x_g @ Wu), gathered rows.
// 128x64x32 tile, 8 warps (4m x 2n), warp tile 32x32, bf16 hi/lo 3-pass fp32 emu.
__global__ __launch_bounds__(256, 1) void gemm1_tc(
    const float* __restrict__ x, const float* __restrict__ Wg,
    const float* __restrict__ Wu, int e)
{
    int cnt = g_cnt[e];
    int row0 = blockIdx.y * BM;
    if (row0 >= cnt) return;
    int col0 = blockIdx.x * BN;

    __shared__ __nv_bfloat16 Ahi[BM][APITCH], Alo[BM][APITCH];
    __shared__ __nv_bfloat16 Bhi[2][BK][BPITCH], Blo[2][BK][BPITCH]; // [0]=gate,[1]=up
    __shared__ int ridx[BM];

    int tid = threadIdx.x;
    int lane = tid & 31, wid = tid >> 5;
    int wm = (wid & 3) * 32, wn = (wid >> 2) * 32;

    if (tid < BM) { int r = row0 + tid; ridx[tid] = (r < cnt) ? g_idx[e][r] : -1; }
    __syncthreads();

    float acc[2][2][4][4]; // [gate/up][mi][nj][frag]
#pragma unroll
    for (int a = 0; a < 2; a++)
#pragma unroll
        for (int b = 0; b < 2; b++)
#pragma unroll
            for (int c = 0; c < 4; c++)
#pragma unroll
                for (int d = 0; d < 4; d++) acc[a][b][c][d] = 0.f;

    float4 pa[4], pbg[2], pbu[2];

    const int NK = H / BK;
    ldA_gather(x, H, ridx, 0, tid, pa);
    ldB(Wg, F, col0, 0, tid, pbg);
    ldB(Wu, F, col0, 0, tid, pbu);
    stA(pa, tid, Ahi, Alo);
    stB(pbg, tid, Bhi[0], Blo[0]);
    stB(pbu, tid, Bhi[1], Blo[1]);
    __syncthreads();

    for (int kt = 0; kt < NK; kt++) {
        if (kt + 1 < NK) {
            ldA_gather(x, H, ridx, (kt + 1) * BK, tid, pa);
            ldB(Wg, F, col0, (kt + 1) * BK, tid, pbg);
            ldB(Wu, F, col0, (kt + 1) * BK, tid, pbu);
        }
#pragma unroll
        for (int ks = 0; ks < 2; ks++) {
            unsigned ah[2][4], al[2][4];
            int ar = wm + (lane & 15), ac = ks * 16 + (lane >> 4) * 8;
#pragma unroll
            for (int mi = 0; mi < 2; mi++) {
                ldsm4(ah[mi], sptr(&Ahi[ar + mi * 16][ac]));
                ldsm4(al[mi], sptr(&Alo[ar + mi * 16][ac]));
            }
            int br = ks * 16 + (lane & 15), bc = wn + (lane >> 4) * 8;
#pragma unroll
            for (int mat = 0; mat < 2; mat++) {
                unsigned bh[2][4], bl[2][4];
#pragma unroll
                for (int nh = 0; nh < 2; nh++) {
                    ldsm4t(bh[nh], sptr(&Bhi[mat][br][bc + nh * 16]));
                    ldsm4t(bl[nh], sptr(&Blo[mat][br][bc + nh * 16]));
                }
#pragma unroll
                for (int mi = 0; mi < 2; mi++)
#pragma unroll
                    for (int nh = 0; nh < 2; nh++)
#pragma unroll
                        for (int s = 0; s < 2; s++) {
                            int nj = nh * 2 + s;
                            mma16816(acc[mat][mi][nj], ah[mi], &bh[nh][s * 2]);
                            mma16816(acc[mat][mi][nj], ah[mi], &bl[nh][s * 2]);
                            mma16816(acc[mat][mi][nj], al[mi], &bh[nh][s * 2]);
                        }
            }
        }
        __syncthreads();
        if (kt + 1 < NK) {
            stA(pa, tid, Ahi, Alo);
            stB(pbg, tid, Bhi[0], Blo[0]);
            stB(pbu, tid, Bhi[1], Blo[1]);
            __syncthreads();
        }
    }

    // epilogue: silu(g)*u -> g_h
#pragma unroll
    for (int mi = 0; mi < 2; mi++)
#pragma unroll
        for (int half = 0; half < 2; half++) {
            int m = wm + mi * 16 + (lane >> 2) + half * 8;
            int r = row0 + m;
            if (r < cnt) {
                float* dst = g_h + (size_t)r * F + col0 + wn + (lane & 3) * 2;
#pragma unroll
                for (int nj = 0; nj < 4; nj++) {
                    float g0 = acc[0][mi][nj][half * 2 + 0];
                    float g1 = acc[0][mi][nj][half * 2 + 1];
                    float u0 = acc[1][mi][nj][half * 2 + 0];
                    float u1 = acc[1][mi][nj][half * 2 + 1];
                    float h0 = g0 / (1.f + __expf(-g0)) * u0;
                    float h1 = g1 / (1.f + __expf(-g1)) * u1;
                    *reinterpret_cast<float2*>(dst + nj * 8) = make_float2(h0, h1);
                }
            }
        }
}

// ---------------------------------------------------------------------------
// GEMM2 (tensor cores): out[tok,:] += w * (h[r,:] @ Wd). Scatter epilogue.
__global__ __launch_bounds__(256, 1) void gemm2_tc(
    const float* __restrict__ Wd, float* __restrict__ out, int e)
{
    int cnt = g_cnt[e];
    int row0 = blockIdx.y * BM;
    if (row0 >= cnt) return;
    int col0 = blockIdx.x * BN;

    __shared__ __nv_bfloat16 Ahi[BM][APITCH], Alo[BM][APITCH];
    __shared__ __nv_bfloat16 Bhi[BK][BPITCH], Blo[BK][BPITCH];

    int tid = threadIdx.x;
    int lane = tid & 31, wid = tid >> 5;
    int wm = (wid & 3) * 32, wn = (wid >> 2) * 32;

    float acc[2][4][4];
#pragma unroll
    for (int b = 0; b < 2; b++)
#pragma unroll
        for (int c = 0; c < 4; c++)
#pragma unroll
            for (int d = 0; d < 4; d++) acc[b][c][d] = 0.f;

    float4 pa[4], pb[2];

    const int NK = F / BK;
    ldA_linear(g_h, F, row0, cnt, 0, tid, pa);
    ldB(Wd, H, col0, 0, tid, pb);
    stA(pa, tid, Ahi, Alo);
    stB(pb, tid, Bhi, Blo);
    __syncthreads();

    for (int kt = 0; kt < NK; kt++) {
        if (kt + 1 < NK) {
            ldA_linear(g_h, F, row0, cnt, (kt + 1) * BK, tid, pa);
            ldB(Wd, H, col0, (kt + 1) * BK, tid, pb);
        }
#pragma unroll
        for (int ks = 0; ks < 2; ks++) {
            unsigned ah[2][4], al[2][4];
            int ar = wm + (lane & 15), ac = ks * 16 + (lane >> 4) * 8;
#pragma unroll
            for (int mi = 0; mi < 2; mi++) {
                ldsm4(ah[mi], sptr(&Ahi[ar + mi * 16][ac]));
                ldsm4(al[mi], sptr(&Alo[ar + mi * 16][ac]));
            }
            int br = ks * 16 + (lane & 15), bc = wn + (lane >> 4) * 8;
            unsigned bh[2][4], bl[2][4];
#pragma unroll
            for (int nh = 0; nh < 2; nh++) {
                ldsm4t(bh[nh], sptr(&Bhi[br][bc + nh * 16]));
                ldsm4t(bl[nh], sptr(&Blo[br][bc + nh * 16]));
            }
#pragma unroll
            for (int mi = 0; mi < 2; mi++)
#pragma unroll
                for (int nh = 0; nh < 2; nh++)
#pragma unroll
                    for (int s = 0; s < 2; s++) {
                        int nj = nh * 2 + s;
                        mma16816(acc[mi][nj], ah[mi], &bh[nh][s * 2]);
                        mma16816(acc[mi][nj], ah[mi], &bl[nh][s * 2]);
                        mma16816(acc[mi][nj], al[mi], &bh[nh][s * 2]);
                    }
        }
        __syncthreads();
        if (kt + 1 < NK) {
            stA(pa, tid, Ahi, Alo);
            stB(pb, tid, Bhi, Blo);
            __syncthreads();
        }
    }

    // epilogue: scatter-accumulate into out (experts serialized by stream order)
#pragma unroll
    for (int mi = 0; mi < 2; mi++)
#pragma unroll
        for (int half = 0; half < 2; half++) {
            int m = wm + mi * 16 + (lane >> 2) + half * 8;
            int r = row0 + m;
            if (r < cnt) {
                int tok = g_idx[e][r];
                float w = g_cw[e][r];
                float* o = out + (size_t)tok * H + col0 + wn + (lane & 3) * 2;
#pragma unroll
                for (int nj = 0; nj < 4; nj++) {
                    o[nj * 8 + 0] += w * acc[mi][nj][half * 2 + 0];
                    o[nj * 8 + 1] += w * acc[mi][nj][half * 2 + 1];
                }
            }
        }
}

// ---------------------------------------------------------------------------
__global__ void finalize_kernel(float* __restrict__ out, int out_size) {
    if (threadIdx.x == 0 && blockIdx.x == 0) {
        float bal = 0.f;
#pragma unroll
        for (int e = 0; e < E; e++)
            bal += ((float)g_cnt[e] / (float)(T * TK)) * (g_sumprob[e] / (float)T);
        out[out_size - 2] = (float)E * bal;
        out[out_size - 1] = g_zsum / (float)T;
    }
}

// ---------------------------------------------------------------------------
extern "C" void kernel_launch(void* const* d_in, const int* in_sizes, int n_in,
                              void* d_out, int out_size) {
    const float* x  = (const float*)d_in[0];   // [4,2048,1024]
    const float* gw = (const float*)d_in[1];   // [1024,8]
    const float* wg = (const float*)d_in[2];   // [8,1024,4096]
    const float* wu = (const float*)d_in[3];   // [8,1024,4096]
    const float* wd = (const float*)d_in[4];   // [8,4096,1024]
    float* out = (float*)d_out;

    zero_kernel<<<512, 256>>>(out);
    router_kernel<<<T / 8, 256>>>(x, gw);

    dim3 g1(F / BN, (T + BM - 1) / BM);   // 64 x 64
    dim3 g2(H / BN, (T + BM - 1) / BM);   // 16 x 64
    for (int e = 0; e < E; e++) {
        gemm1_tc<<<g1, 256>>>(x, wg + (size_t)e * H * F, wu + (size_t)e * H * F, e);
        gemm2_tc<<<g2, 256>>>(wd + (size_t)e * F * H, out, e);
    }

    finalize_kernel<<<1, 32>>>(out, out_size);
}

// round 7
// speedup vs baseline: 1.1614x; 1.1611x over previous
#include <cuda_runtime.h>
#include <cuda_bf16.h>
#include <stdint.h>
#include <math.h>

#define H 1024
#define F 4096
#define E 8
#define TK 2
#define T 8192

#define BM 128
#define BN 64
#define BK 32
#define NSTAGE 3

// smem pitches (bf16 elements)
#define APITCH 40            // 80 bytes/row: conflict-free ldmatrix, 16B-aligned granules
#define BPITCH 72            // 144 bytes/row
#define A_BYTES (BM * APITCH * 2)   // 10240
#define B_BYTES (BK * BPITCH * 2)   // 4608
#define STAGE1  (2 * A_BYTES + 4 * B_BYTES)   // 38912 (Ahi,Alo,Bgh,Bgl,Buh,Bul)
#define STAGE2  (2 * A_BYTES + 2 * B_BYTES)   // 29696 (Ahi,Alo,Bh,Bl)
#define SMEM1   (NSTAGE * STAGE1 + 512)
#define SMEM2   (NSTAGE * STAGE2)

// ---- device scratch (static: no allocations allowed) ----
__device__ int   g_cnt[E];
__device__ int   g_idx[E][T];
__device__ float g_cw[E][T];
__device__ float g_sumprob[E];
__device__ float g_zsum;

// preconverted bf16 hi/lo operands (all 16B-aligned for cp.async)
__device__ __align__(16) __nv_bfloat16 g_xh[(size_t)T * H];
__device__ __align__(16) __nv_bfloat16 g_xl[(size_t)T * H];
__device__ __align__(16) __nv_bfloat16 g_wgh[(size_t)E * H * F];
__device__ __align__(16) __nv_bfloat16 g_wgl[(size_t)E * H * F];
__device__ __align__(16) __nv_bfloat16 g_wuh[(size_t)E * H * F];
__device__ __align__(16) __nv_bfloat16 g_wul[(size_t)E * H * F];
__device__ __align__(16) __nv_bfloat16 g_wdh[(size_t)E * F * H];
__device__ __align__(16) __nv_bfloat16 g_wdl[(size_t)E * F * H];
__device__ __align__(16) __nv_bfloat16 g_hh[(size_t)T * F];
__device__ __align__(16) __nv_bfloat16 g_hl[(size_t)T * F];

// ---------------------------------------------------------------------------
// helpers
__device__ __forceinline__ unsigned sptr(const void* p) {
    return (unsigned)__cvta_generic_to_shared(p);
}
__device__ __forceinline__ void ldsm4(unsigned* r, unsigned a) {
    asm volatile("ldmatrix.sync.aligned.m8n8.x4.shared.b16 {%0,%1,%2,%3}, [%4];"
                 : "=r"(r[0]), "=r"(r[1]), "=r"(r[2]), "=r"(r[3]) : "r"(a));
}
__device__ __forceinline__ void ldsm4t(unsigned* r, unsigned a) {
    asm volatile("ldmatrix.sync.aligned.m8n8.x4.trans.shared.b16 {%0,%1,%2,%3}, [%4];"
                 : "=r"(r[0]), "=r"(r[1]), "=r"(r[2]), "=r"(r[3]) : "r"(a));
}
__device__ __forceinline__ void mma16816(float* d, const unsigned* a, const unsigned* b) {
    asm volatile("mma.sync.aligned.m16n8k16.row.col.f32.bf16.bf16.f32 "
                 "{%0,%1,%2,%3},{%4,%5,%6,%7},{%8,%9},{%0,%1,%2,%3};"
                 : "+f"(d[0]), "+f"(d[1]), "+f"(d[2]), "+f"(d[3])
                 : "r"(a[0]), "r"(a[1]), "r"(a[2]), "r"(a[3]), "r"(b[0]), "r"(b[1]));
}
__device__ __forceinline__ void split2(float x, float y, unsigned& hi, unsigned& lo) {
    __nv_bfloat16 hx = __float2bfloat16(x);
    __nv_bfloat16 hy = __float2bfloat16(y);
    __nv_bfloat16 lx = __float2bfloat16(x - __bfloat162float(hx));
    __nv_bfloat16 ly = __float2bfloat16(y - __bfloat162float(hy));
    __nv_bfloat162 h = __halves2bfloat162(hx, hy);
    __nv_bfloat162 l = __halves2bfloat162(lx, ly);
    hi = *reinterpret_cast<unsigned*>(&h);
    lo = *reinterpret_cast<unsigned*>(&l);
}
__device__ __forceinline__ void cpasync16(unsigned dst, const void* src, int sz) {
    asm volatile("cp.async.cg.shared.global [%0], [%1], 16, %2;\n"
                 :: "r"(dst), "l"(src), "r"(sz));
}
__device__ __forceinline__ void cpcommit() { asm volatile("cp.async.commit_group;\n"); }
__device__ __forceinline__ void cpwait1()  { asm volatile("cp.async.wait_group 1;\n"); }

// ---------------------------------------------------------------------------
// fp32 -> bf16 hi/lo converter. which: 0=wg, 1=wu, 2=wd, 3=x
__global__ void convert_kernel(const float4* __restrict__ src, size_t n4, int which) {
    uint2* dh; uint2* dl;
    if (which == 0)      { dh = (uint2*)g_wgh; dl = (uint2*)g_wgl; }
    else if (which == 1) { dh = (uint2*)g_wuh; dl = (uint2*)g_wul; }
    else if (which == 2) { dh = (uint2*)g_wdh; dl = (uint2*)g_wdl; }
    else                 { dh = (uint2*)g_xh;  dl = (uint2*)g_xl;  }
    size_t stride = (size_t)gridDim.x * blockDim.x;
    for (size_t i = (size_t)blockIdx.x * blockDim.x + threadIdx.x; i < n4; i += stride) {
        float4 v = src[i];
        unsigned h0, l0, h1, l1;
        split2(v.x, v.y, h0, l0);
        split2(v.z, v.w, h1, l1);
        dh[i] = make_uint2(h0, h1);
        dl[i] = make_uint2(l0, l1);
    }
}

// ---------------------------------------------------------------------------
__global__ void zero_kernel(float* __restrict__ out) {
    size_t n = (size_t)T * H;
    size_t stride = (size_t)gridDim.x * blockDim.x;
    for (size_t i = (size_t)blockIdx.x * blockDim.x + threadIdx.x; i < n; i += stride)
        out[i] = 0.f;
    if (blockIdx.x == 0 && threadIdx.x < E) {
        g_cnt[threadIdx.x] = 0;
        g_sumprob[threadIdx.x] = 0.f;
    }
    if (blockIdx.x == 0 && threadIdx.x == E) g_zsum = 0.f;
}

// ---------------------------------------------------------------------------
// One warp per token: logits -> softmax -> top-2 -> gather lists + aux losses.
__global__ void router_kernel(const float* __restrict__ x,
                              const float* __restrict__ gw) {
    int warp = threadIdx.x >> 5;
    int lane = threadIdx.x & 31;
    int t = blockIdx.x * (blockDim.x >> 5) + warp;
    if (t >= T) return;

    const float* xr = x + (size_t)t * H;
    float acc[E];
#pragma unroll
    for (int e = 0; e < E; e++) acc[e] = 0.f;

    for (int h = lane; h < H; h += 32) {
        float xv = xr[h];
#pragma unroll
        for (int e = 0; e < E; e++) acc[e] += xv * gw[h * E + e];
    }
#pragma unroll
    for (int off = 16; off; off >>= 1) {
#pragma unroll
        for (int e = 0; e < E; e++)
            acc[e] += __shfl_down_sync(0xffffffffu, acc[e], off);
    }

    if (lane == 0) {
        float m = acc[0];
#pragma unroll
        for (int e = 1; e < E; e++) m = fmaxf(m, acc[e]);
        float p[E], s = 0.f;
#pragma unroll
        for (int e = 0; e < E; e++) { p[e] = __expf(acc[e] - m); s += p[e]; }
        float inv = 1.f / s;
        float lse = m + logf(s);
        atomicAdd(&g_zsum, lse * lse);

        int i1 = 0; float p1 = -1.f;
#pragma unroll
        for (int e = 0; e < E; e++) {
            float pe = p[e] * inv;
            p[e] = pe;
            atomicAdd(&g_sumprob[e], pe);
            if (pe > p1) { p1 = pe; i1 = e; }
        }
        int i2 = -1; float p2 = -1.f;
#pragma unroll
        for (int e = 0; e < E; e++) {
            if (e != i1 && p[e] > p2) { p2 = p[e]; i2 = e; }
        }
        float rs = 1.f / (p1 + p2);
        float w1 = p1 * rs, w2 = p2 * rs;

        int pos1 = atomicAdd(&g_cnt[i1], 1);
        g_idx[i1][pos1] = t; g_cw[i1][pos1] = w1;
        int pos2 = atomicAdd(&g_cnt[i2], 1);
        g_idx[i2][pos2] = t; g_cw[i2][pos2] = w2;
    }
}

// ---------------------------------------------------------------------------
// cp.async stage issue for gemm1: A gathered from g_xh/g_xl, B = Wg/Wu hi/lo.
__device__ __forceinline__ void issue1(int k0, unsigned buf, const int* __restrict__ ridx,
                                       const __nv_bfloat16* __restrict__ wgh,
                                       const __nv_bfloat16* __restrict__ wgl,
                                       const __nv_bfloat16* __restrict__ wuh,
                                       const __nv_bfloat16* __restrict__ wul,
                                       int col0, int tid) {
#pragma unroll
    for (int i = 0; i < 2; i++) {
        int g = tid + i * 256;
        int r = g >> 2, q = g & 3;
        int gr = ridx[r];
        int sz = (gr >= 0) ? 16 : 0;
        size_t soff = (size_t)(gr >= 0 ? gr : 0) * H + k0 + q * 8;
        unsigned da = buf + r * (APITCH * 2) + q * 16;
        cpasync16(da,           g_xh + soff, sz);
        cpasync16(da + A_BYTES, g_xl + soff, sz);
    }
    {
        int r = tid >> 3, q = tid & 7;
        size_t soff = (size_t)(k0 + r) * F + col0 + q * 8;
        unsigned db = buf + 2 * A_BYTES + r * (BPITCH * 2) + q * 16;
        cpasync16(db,               wgh + soff, 16);
        cpasync16(db + B_BYTES,     wgl + soff, 16);
        cpasync16(db + 2 * B_BYTES, wuh + soff, 16);
        cpasync16(db + 3 * B_BYTES, wul + soff, 16);
    }
}

// GEMM1: h = silu(x@Wg) * (x@Wu) on gathered rows. 128x64x32, 8 warps,
// bf16 hi/lo 3-pass, 3-stage cp.async pipeline. Output -> g_hh/g_hl (bf16 hi/lo).
__global__ __launch_bounds__(256, 1) void gemm1_tc(int e) {
    int cnt = g_cnt[e];
    int row0 = blockIdx.y * BM;
    if (row0 >= cnt) return;
    int col0 = blockIdx.x * BN;

    const __nv_bfloat16* wgh = g_wgh + (size_t)e * H * F;
    const __nv_bfloat16* wgl = g_wgl + (size_t)e * H * F;
    const __nv_bfloat16* wuh = g_wuh + (size_t)e * H * F;
    const __nv_bfloat16* wul = g_wul + (size_t)e * H * F;

    extern __shared__ char smem[];
    unsigned sbase = sptr(smem);
    int* ridx = (int*)(smem + NSTAGE * STAGE1);

    int tid = threadIdx.x;
    int lane = tid & 31, wid = tid >> 5;
    int wm = (wid & 3) * 32, wn = (wid >> 2) * 32;

    if (tid < BM) { int r = row0 + tid; ridx[tid] = (r < cnt) ? g_idx[e][r] : -1; }
    __syncthreads();

    float acc[2][2][4][4];
#pragma unroll
    for (int a = 0; a < 2; a++)
#pragma unroll
        for (int b = 0; b < 2; b++)
#pragma unroll
            for (int c = 0; c < 4; c++)
#pragma unroll
                for (int d = 0; d < 4; d++) acc[a][b][c][d] = 0.f;

    const int NK = H / BK;
#pragma unroll
    for (int s = 0; s < NSTAGE - 1; s++) {
        issue1(s * BK, sbase + s * STAGE1, ridx, wgh, wgl, wuh, wul, col0, tid);
        cpcommit();
    }
    cpwait1();
    __syncthreads();

    for (int kt = 0; kt < NK; kt++) {
        int kn = kt + NSTAGE - 1;
        if (kn < NK)
            issue1(kn * BK, sbase + (kn % NSTAGE) * STAGE1, ridx, wgh, wgl, wuh, wul, col0, tid);
        cpcommit();

        unsigned sb = sbase + (kt % NSTAGE) * STAGE1;
#pragma unroll
        for (int ks = 0; ks < 2; ks++) {
            unsigned ah[2][4], al[2][4];
            int ar = wm + (lane & 15);
            int ac = ks * 16 + (lane >> 4) * 8;
#pragma unroll
            for (int mi = 0; mi < 2; mi++) {
                unsigned aoff = ((ar + mi * 16) * APITCH + ac) * 2;
                ldsm4(ah[mi], sb + aoff);
                ldsm4(al[mi], sb + A_BYTES + aoff);
            }
            int br = ks * 16 + (lane & 15), bc = wn + (lane >> 4) * 8;
#pragma unroll
            for (int mat = 0; mat < 2; mat++) {
                unsigned bbase = sb + 2 * A_BYTES + mat * 2 * B_BYTES;
                unsigned bh[2][4], bl[2][4];
#pragma unroll
                for (int nh = 0; nh < 2; nh++) {
                    unsigned boff = (br * BPITCH + bc + nh * 16) * 2;
                    ldsm4t(bh[nh], bbase + boff);
                    ldsm4t(bl[nh], bbase + B_BYTES + boff);
                }
#pragma unroll
                for (int mi = 0; mi < 2; mi++)
#pragma unroll
                    for (int nh = 0; nh < 2; nh++)
#pragma unroll
                        for (int s = 0; s < 2; s++) {
                            int nj = nh * 2 + s;
                            mma16816(acc[mat][mi][nj], ah[mi], &bh[nh][s * 2]);
                            mma16816(acc[mat][mi][nj], ah[mi], &bl[nh][s * 2]);
                            mma16816(acc[mat][mi][nj], al[mi], &bh[nh][s * 2]);
                        }
            }
        }
        cpwait1();
        __syncthreads();
    }

    // epilogue: silu(g)*u -> g_hh/g_hl (bf16 hi/lo)
#pragma unroll
    for (int mi = 0; mi < 2; mi++)
#pragma unroll
        for (int half = 0; half < 2; half++) {
            int m = wm + mi * 16 + (lane >> 2) + half * 8;
            int r = row0 + m;
            if (r < cnt) {
                size_t base = (size_t)r * F + col0 + wn + (lane & 3) * 2;
#pragma unroll
                for (int nj = 0; nj < 4; nj++) {
                    float g0 = acc[0][mi][nj][half * 2 + 0];
                    float g1 = acc[0][mi][nj][half * 2 + 1];
                    float u0 = acc[1][mi][nj][half * 2 + 0];
                    float u1 = acc[1][mi][nj][half * 2 + 1];
                    float h0 = g0 / (1.f + __expf(-g0)) * u0;
                    float h1 = g1 / (1.f + __expf(-g1)) * u1;
                    unsigned hh, hl;
                    split2(h0, h1, hh, hl);
                    *reinterpret_cast<unsigned*>(g_hh + base + nj * 8) = hh;
                    *reinterpret_cast<unsigned*>(g_hl + base + nj * 8) = hl;
                }
            }
        }
}

// ---------------------------------------------------------------------------
// cp.async stage issue for gemm2: A linear rows from g_hh/g_hl, B = Wd hi/lo.
__device__ __forceinline__ void issue2(int k0, unsigned buf, int row0, int cnt,
                                       const __nv_bfloat16* __restrict__ wdh,
                                       const __nv_bfloat16* __restrict__ wdl,
                                       int col0, int tid) {
#pragma unroll
    for (int i = 0; i < 2; i++) {
        int g = tid + i * 256;
        int r = g >> 2, q = g & 3;
        int gr = row0 + r;
        int sz = (gr < cnt) ? 16 : 0;
        size_t soff = (size_t)(gr < cnt ? gr : 0) * F + k0 + q * 8;
        unsigned da = buf + r * (APITCH * 2) + q * 16;
        cpasync16(da,           g_hh + soff, sz);
        cpasync16(da + A_BYTES, g_hl + soff, sz);
    }
    {
        int r = tid >> 3, q = tid & 7;
        size_t soff = (size_t)(k0 + r) * H + col0 + q * 8;
        unsigned db = buf + 2 * A_BYTES + r * (BPITCH * 2) + q * 16;
        cpasync16(db,           wdh + soff, 16);
        cpasync16(db + B_BYTES, wdl + soff, 16);
    }
}

// GEMM2: out[tok,:] += w * (h @ Wd). Scatter epilogue.
__global__ __launch_bounds__(256, 1) void gemm2_tc(float* __restrict__ out, int e) {
    int cnt = g_cnt[e];
    int row0 = blockIdx.y * BM;
    if (row0 >= cnt) return;
    int col0 = blockIdx.x * BN;

    const __nv_bfloat16* wdh = g_wdh + (size_t)e * F * H;
    const __nv_bfloat16* wdl = g_wdl + (size_t)e * F * H;

    extern __shared__ char smem[];
    unsigned sbase = sptr(smem);

    int tid = threadIdx.x;
    int lane = tid & 31, wid = tid >> 5;
    int wm = (wid & 3) * 32, wn = (wid >> 2) * 32;

    float acc[2][4][4];
#pragma unroll
    for (int b = 0; b < 2; b++)
#pragma unroll
        for (int c = 0; c < 4; c++)
#pragma unroll
            for (int d = 0; d < 4; d++) acc[b][c][d] = 0.f;

    const int NK = F / BK;
#pragma unroll
    for (int s = 0; s < NSTAGE - 1; s++) {
        issue2(s * BK, sbase + s * STAGE2, row0, cnt, wdh, wdl, col0, tid);
        cpcommit();
    }
    cpwait1();
    __syncthreads();

    for (int kt = 0; kt < NK; kt++) {
        int kn = kt + NSTAGE - 1;
        if (kn < NK)
            issue2(kn * BK, sbase + (kn % NSTAGE) * STAGE2, row0, cnt, wdh, wdl, col0, tid);
        cpcommit();

        unsigned sb = sbase + (kt % NSTAGE) * STAGE2;
#pragma unroll
        for (int ks = 0; ks < 2; ks++) {
            unsigned ah[2][4], al[2][4];
            int ar = wm + (lane & 15);
            int ac = ks * 16 + (lane >> 4) * 8;
#pragma unroll
            for (int mi = 0; mi < 2; mi++) {
                unsigned aoff = ((ar + mi * 16) * APITCH + ac) * 2;
                ldsm4(ah[mi], sb + aoff);
                ldsm4(al[mi], sb + A_BYTES + aoff);
            }
            int br = ks * 16 + (lane & 15), bc = wn + (lane >> 4) * 8;
            unsigned bbase = sb + 2 * A_BYTES;
            unsigned bh[2][4], bl[2][4];
#pragma unroll
            for (int nh = 0; nh < 2; nh++) {
                unsigned boff = (br * BPITCH + bc + nh * 16) * 2;
                ldsm4t(bh[nh], bbase + boff);
                ldsm4t(bl[nh], bbase + B_BYTES + boff);
            }
#pragma unroll
            for (int mi = 0; mi < 2; mi++)
#pragma unroll
                for (int nh = 0; nh < 2; nh++)
#pragma unroll
                    for (int s = 0; s < 2; s++) {
                        int nj = nh * 2 + s;
                        mma16816(acc[mi][nj], ah[mi], &bh[nh][s * 2]);
                        mma16816(acc[mi][nj], ah[mi], &bl[nh][s * 2]);
                        mma16816(acc[mi][nj], al[mi], &bh[nh][s * 2]);
                    }
        }
        cpwait1();
        __syncthreads();
    }

    // epilogue: scatter-accumulate (experts serialized by stream order)
#pragma unroll
    for (int mi = 0; mi < 2; mi++)
#pragma unroll
        for (int half = 0; half < 2; half++) {
            int m = wm + mi * 16 + (lane >> 2) + half * 8;
            int r = row0 + m;
            if (r < cnt) {
                int tok = g_idx[e][r];
                float w = g_cw[e][r];
                float* o = out + (size_t)tok * H + col0 + wn + (lane & 3) * 2;
#pragma unroll
                for (int nj = 0; nj < 4; nj++) {
                    o[nj * 8 + 0] += w * acc[mi][nj][half * 2 + 0];
                    o[nj * 8 + 1] += w * acc[mi][nj][half * 2 + 1];
                }
            }
        }
}

// ---------------------------------------------------------------------------
__global__ void finalize_kernel(float* __restrict__ out, int out_size) {
    if (threadIdx.x == 0 && blockIdx.x == 0) {
        float bal = 0.f;
#pragma unroll
        for (int e = 0; e < E; e++)
            bal += ((float)g_cnt[e] / (float)(T * TK)) * (g_sumprob[e] / (float)T);
        out[out_size - 2] = (float)E * bal;
        out[out_size - 1] = g_zsum / (float)T;
    }
}

// ---------------------------------------------------------------------------
extern "C" void kernel_launch(void* const* d_in, const int* in_sizes, int n_in,
                              void* d_out, int out_size) {
    const float* x  = (const float*)d_in[0];   // [4,2048,1024]
    const float* gw = (const float*)d_in[1];   // [1024,8]
    const float* wg = (const float*)d_in[2];   // [8,1024,4096]
    const float* wu = (const float*)d_in[3];   // [8,1024,4096]
    const float* wd = (const float*)d_in[4];   // [8,4096,1024]
    float* out = (float*)d_out;

    cudaFuncSetAttribute(gemm1_tc, cudaFuncAttributeMaxDynamicSharedMemorySize, SMEM1);
    cudaFuncSetAttribute(gemm2_tc, cudaFuncAttributeMaxDynamicSharedMemorySize, SMEM2);

    zero_kernel<<<512, 256>>>(out);

    size_t nw = (size_t)E * H * F / 4;
    convert_kernel<<<2048, 256>>>((const float4*)wg, nw, 0);
    convert_kernel<<<2048, 256>>>((const float4*)wu, nw, 1);
    convert_kernel<<<2048, 256>>>((const float4*)wd, nw, 2);
    convert_kernel<<<1024, 256>>>((const float4*)x, (size_t)T * H / 4, 3);

    router_kernel<<<T / 8, 256>>>(x, gw);

    dim3 g1(F / BN, T / BM);   // 64 x 64
    dim3 g2(H / BN, T / BM);   // 16 x 64
    for (int e = 0; e < E; e++) {
        gemm1_tc<<<g1, 256, SMEM1>>>(e);
        gemm2_tc<<<g2, 256, SMEM2>>>(out, e);
    }

    finalize_kernel<<<1, 32>>>(out, out_size);
}

// round 8
// speedup vs baseline: 1.1647x; 1.0029x over previous
#include <cuda_runtime.h>
#include <cuda_bf16.h>
#include <stdint.h>
#include <math.h>

#define H 1024
#define F 4096
#define E 8
#define TK 2
#define T 8192

#define BM 128
#define BN 64
#define BK 32
#define NSTAGE 3

// smem pitches (bf16 elements)
#define APITCH 40            // 80 bytes/row: conflict-free ldmatrix, 16B-aligned granules
#define BPITCH 72            // 144 bytes/row
#define A_BYTES (BM * APITCH * 2)   // 10240
#define B_BYTES (BK * BPITCH * 2)   // 4608
#define STAGE1  (2 * A_BYTES + 4 * B_BYTES)   // 38912 (Ahi,Alo,Bgh,Bgl,Buh,Bul)
#define STAGE2  (2 * A_BYTES + 2 * B_BYTES)   // 29696 (Ahi,Alo,Bh,Bl)
#define SMEM1   (NSTAGE * STAGE1 + 512)
#define SMEM2   (NSTAGE * STAGE2)

// ---- device scratch (static: no allocations allowed) ----
__device__ int   g_cnt[E];
__device__ int   g_idx[E][T];
__device__ float g_cw[E][T];
__device__ float g_sumprob[E];
__device__ float g_zsum;

// preconverted bf16 hi/lo operands (all 16B-aligned for cp.async)
__device__ __align__(16) __nv_bfloat16 g_xh[(size_t)T * H];
__device__ __align__(16) __nv_bfloat16 g_xl[(size_t)T * H];
__device__ __align__(16) __nv_bfloat16 g_wgh[(size_t)E * H * F];
__device__ __align__(16) __nv_bfloat16 g_wgl[(size_t)E * H * F];
__device__ __align__(16) __nv_bfloat16 g_wuh[(size_t)E * H * F];
__device__ __align__(16) __nv_bfloat16 g_wul[(size_t)E * H * F];
__device__ __align__(16) __nv_bfloat16 g_wdh[(size_t)E * F * H];
__device__ __align__(16) __nv_bfloat16 g_wdl[(size_t)E * F * H];
__device__ __align__(16) __nv_bfloat16 g_hh[(size_t)T * F];
__device__ __align__(16) __nv_bfloat16 g_hl[(size_t)T * F];

// ---------------------------------------------------------------------------
// helpers
__device__ __forceinline__ unsigned sptr(const void* p) {
    return (unsigned)__cvta_generic_to_shared(p);
}
__device__ __forceinline__ void ldsm4(unsigned* r, unsigned a) {
    asm volatile("ldmatrix.sync.aligned.m8n8.x4.shared.b16 {%0,%1,%2,%3}, [%4];"
                 : "=r"(r[0]), "=r"(r[1]), "=r"(r[2]), "=r"(r[3]) : "r"(a));
}
__device__ __forceinline__ void ldsm4t(unsigned* r, unsigned a) {
    asm volatile("ldmatrix.sync.aligned.m8n8.x4.trans.shared.b16 {%0,%1,%2,%3}, [%4];"
                 : "=r"(r[0]), "=r"(r[1]), "=r"(r[2]), "=r"(r[3]) : "r"(a));
}
__device__ __forceinline__ void mma16816(float* d, const unsigned* a, const unsigned* b) {
    asm volatile("mma.sync.aligned.m16n8k16.row.col.f32.bf16.bf16.f32 "
                 "{%0,%1,%2,%3},{%4,%5,%6,%7},{%8,%9},{%0,%1,%2,%3};"
                 : "+f"(d[0]), "+f"(d[1]), "+f"(d[2]), "+f"(d[3])
                 : "r"(a[0]), "r"(a[1]), "r"(a[2]), "r"(a[3]), "r"(b[0]), "r"(b[1]));
}
__device__ __forceinline__ void split2(float x, float y, unsigned& hi, unsigned& lo) {
    __nv_bfloat16 hx = __float2bfloat16(x);
    __nv_bfloat16 hy = __float2bfloat16(y);
    __nv_bfloat16 lx = __float2bfloat16(x - __bfloat162float(hx));
    __nv_bfloat16 ly = __float2bfloat16(y - __bfloat162float(hy));
    __nv_bfloat162 h = __halves2bfloat162(hx, hy);
    __nv_bfloat162 l = __halves2bfloat162(lx, ly);
    hi = *reinterpret_cast<unsigned*>(&h);
    lo = *reinterpret_cast<unsigned*>(&l);
}
__device__ __forceinline__ void cpasync16(unsigned dst, const void* src, int sz) {
    asm volatile("cp.async.cg.shared.global [%0], [%1], 16, %2;\n"
                 :: "r"(dst), "l"(src), "r"(sz));
}
__device__ __forceinline__ void cpcommit() { asm volatile("cp.async.commit_group;\n"); }
__device__ __forceinline__ void cpwait1()  { asm volatile("cp.async.wait_group 1;\n"); }

// ---------------------------------------------------------------------------
// fp32 -> bf16 hi/lo converter. which: 0=wg, 1=wu, 2=wd, 3=x
__global__ void convert_kernel(const float4* __restrict__ src, size_t n4, int which) {
    uint2* dh; uint2* dl;
    if (which == 0)      { dh = (uint2*)g_wgh; dl = (uint2*)g_wgl; }
    else if (which == 1) { dh = (uint2*)g_wuh; dl = (uint2*)g_wul; }
    else if (which == 2) { dh = (uint2*)g_wdh; dl = (uint2*)g_wdl; }
    else                 { dh = (uint2*)g_xh;  dl = (uint2*)g_xl;  }
    size_t stride = (size_t)gridDim.x * blockDim.x;
    for (size_t i = (size_t)blockIdx.x * blockDim.x + threadIdx.x; i < n4; i += stride) {
        float4 v = src[i];
        unsigned h0, l0, h1, l1;
        split2(v.x, v.y, h0, l0);
        split2(v.z, v.w, h1, l1);
        dh[i] = make_uint2(h0, h1);
        dl[i] = make_uint2(l0, l1);
    }
}

// ---------------------------------------------------------------------------
__global__ void zero_kernel(float* __restrict__ out) {
    size_t n = (size_t)T * H;
    size_t stride = (size_t)gridDim.x * blockDim.x;
    for (size_t i = (size_t)blockIdx.x * blockDim.x + threadIdx.x; i < n; i += stride)
        out[i] = 0.f;
    if (blockIdx.x == 0 && threadIdx.x < E) {
        g_cnt[threadIdx.x] = 0;
        g_sumprob[threadIdx.x] = 0.f;
    }
    if (blockIdx.x == 0 && threadIdx.x == E) g_zsum = 0.f;
}

// ---------------------------------------------------------------------------
// One warp per token: logits -> softmax -> top-2 -> gather lists + aux losses.
__global__ void router_kernel(const float* __restrict__ x,
                              const float* __restrict__ gw) {
    int warp = threadIdx.x >> 5;
    int lane = threadIdx.x & 31;
    int t = blockIdx.x * (blockDim.x >> 5) + warp;
    if (t >= T) return;

    const float* xr = x + (size_t)t * H;
    float acc[E];
#pragma unroll
    for (int e = 0; e < E; e++) acc[e] = 0.f;

    for (int h = lane; h < H; h += 32) {
        float xv = xr[h];
#pragma unroll
        for (int e = 0; e < E; e++) acc[e] += xv * gw[h * E + e];
    }
#pragma unroll
    for (int off = 16; off; off >>= 1) {
#pragma unroll
        for (int e = 0; e < E; e++)
            acc[e] += __shfl_down_sync(0xffffffffu, acc[e], off);
    }

    if (lane == 0) {
        float m = acc[0];
#pragma unroll
        for (int e = 1; e < E; e++) m = fmaxf(m, acc[e]);
        float p[E], s = 0.f;
#pragma unroll
        for (int e = 0; e < E; e++) { p[e] = __expf(acc[e] - m); s += p[e]; }
        float inv = 1.f / s;
        float lse = m + logf(s);
        atomicAdd(&g_zsum, lse * lse);

        int i1 = 0; float p1 = -1.f;
#pragma unroll
        for (int e = 0; e < E; e++) {
            float pe = p[e] * inv;
            p[e] = pe;
            atomicAdd(&g_sumprob[e], pe);
            if (pe > p1) { p1 = pe; i1 = e; }
        }
        int i2 = -1; float p2 = -1.f;
#pragma unroll
        for (int e = 0; e < E; e++) {
            if (e != i1 && p[e] > p2) { p2 = p[e]; i2 = e; }
        }
        float rs = 1.f / (p1 + p2);
        float w1 = p1 * rs, w2 = p2 * rs;

        int pos1 = atomicAdd(&g_cnt[i1], 1);
        g_idx[i1][pos1] = t; g_cw[i1][pos1] = w1;
        int pos2 = atomicAdd(&g_cnt[i2], 1);
        g_idx[i2][pos2] = t; g_cw[i2][pos2] = w2;
    }
}

// ---------------------------------------------------------------------------
// cp.async stage issue for gemm1: A gathered from g_xh/g_xl, B = Wg/Wu hi/lo.
__device__ __forceinline__ void issue1(int k0, unsigned buf, const int* __restrict__ ridx,
                                       const __nv_bfloat16* __restrict__ wgh,
                                       const __nv_bfloat16* __restrict__ wgl,
                                       const __nv_bfloat16* __restrict__ wuh,
                                       const __nv_bfloat16* __restrict__ wul,
                                       int col0, int tid) {
#pragma unroll
    for (int i = 0; i < 2; i++) {
        int g = tid + i * 256;
        int r = g >> 2, q = g & 3;
        int gr = ridx[r];
        int sz = (gr >= 0) ? 16 : 0;
        size_t soff = (size_t)(gr >= 0 ? gr : 0) * H + k0 + q * 8;
        unsigned da = buf + r * (APITCH * 2) + q * 16;
        cpasync16(da,           g_xh + soff, sz);
        cpasync16(da + A_BYTES, g_xl + soff, sz);
    }
    {
        int r = tid >> 3, q = tid & 7;
        size_t soff = (size_t)(k0 + r) * F + col0 + q * 8;
        unsigned db = buf + 2 * A_BYTES + r * (BPITCH * 2) + q * 16;
        cpasync16(db,               wgh + soff, 16);
        cpasync16(db + B_BYTES,     wgl + soff, 16);
        cpasync16(db + 2 * B_BYTES, wuh + soff, 16);
        cpasync16(db + 3 * B_BYTES, wul + soff, 16);
    }
}

// GEMM1: h = silu(x@Wg) * (x@Wu) on gathered rows. 128x64x32, 8 warps,
// bf16 hi/lo 3-pass, 3-stage cp.async pipeline. Output -> g_hh/g_hl (bf16 hi/lo).
__global__ __launch_bounds__(256, 1) void gemm1_tc(int e) {
    int cnt = g_cnt[e];
    int row0 = blockIdx.y * BM;
    if (row0 >= cnt) return;
    int col0 = blockIdx.x * BN;

    const __nv_bfloat16* wgh = g_wgh + (size_t)e * H * F;
    const __nv_bfloat16* wgl = g_wgl + (size_t)e * H * F;
    const __nv_bfloat16* wuh = g_wuh + (size_t)e * H * F;
    const __nv_bfloat16* wul = g_wul + (size_t)e * H * F;

    extern __shared__ char smem[];
    unsigned sbase = sptr(smem);
    int* ridx = (int*)(smem + NSTAGE * STAGE1);

    int tid = threadIdx.x;
    int lane = tid & 31, wid = tid >> 5;
    int wm = (wid & 3) * 32, wn = (wid >> 2) * 32;

    if (tid < BM) { int r = row0 + tid; ridx[tid] = (r < cnt) ? g_idx[e][r] : -1; }
    __syncthreads();

    float acc[2][2][4][4];
#pragma unroll
    for (int a = 0; a < 2; a++)
#pragma unroll
        for (int b = 0; b < 2; b++)
#pragma unroll
            for (int c = 0; c < 4; c++)
#pragma unroll
                for (int d = 0; d < 4; d++) acc[a][b][c][d] = 0.f;

    const int NK = H / BK;
#pragma unroll
    for (int s = 0; s < NSTAGE - 1; s++) {
        issue1(s * BK, sbase + s * STAGE1, ridx, wgh, wgl, wuh, wul, col0, tid);
        cpcommit();
    }
    cpwait1();
    __syncthreads();

    for (int kt = 0; kt < NK; kt++) {
        int kn = kt + NSTAGE - 1;
        if (kn < NK)
            issue1(kn * BK, sbase + (kn % NSTAGE) * STAGE1, ridx, wgh, wgl, wuh, wul, col0, tid);
        cpcommit();

        unsigned sb = sbase + (kt % NSTAGE) * STAGE1;
#pragma unroll
        for (int ks = 0; ks < 2; ks++) {
            unsigned ah[2][4], al[2][4];
            int ar = wm + (lane & 15);
            int ac = ks * 16 + (lane >> 4) * 8;
#pragma unroll
            for (int mi = 0; mi < 2; mi++) {
                unsigned aoff = ((ar + mi * 16) * APITCH + ac) * 2;
                ldsm4(ah[mi], sb + aoff);
                ldsm4(al[mi], sb + A_BYTES + aoff);
            }
            int br = ks * 16 + (lane & 15), bc = wn + (lane >> 4) * 8;
#pragma unroll
            for (int mat = 0; mat < 2; mat++) {
                unsigned bbase = sb + 2 * A_BYTES + mat * 2 * B_BYTES;
                unsigned bh[2][4], bl[2][4];
#pragma unroll
                for (int nh = 0; nh < 2; nh++) {
                    unsigned boff = (br * BPITCH + bc + nh * 16) * 2;
                    ldsm4t(bh[nh], bbase + boff);
                    ldsm4t(bl[nh], bbase + B_BYTES + boff);
                }
#pragma unroll
                for (int mi = 0; mi < 2; mi++)
#pragma unroll
                    for (int nh = 0; nh < 2; nh++)
#pragma unroll
                        for (int s = 0; s < 2; s++) {
                            int nj = nh * 2 + s;
                            mma16816(acc[mat][mi][nj], ah[mi], &bh[nh][s * 2]);
                            mma16816(acc[mat][mi][nj], ah[mi], &bl[nh][s * 2]);
                            mma16816(acc[mat][mi][nj], al[mi], &bh[nh][s * 2]);
                        }
            }
        }
        cpwait1();
        __syncthreads();
    }

    // epilogue: silu(g)*u -> g_hh/g_hl (bf16 hi/lo)
#pragma unroll
    for (int mi = 0; mi < 2; mi++)
#pragma unroll
        for (int half = 0; half < 2; half++) {
            int m = wm + mi * 16 + (lane >> 2) + half * 8;
            int r = row0 + m;
            if (r < cnt) {
                size_t base = (size_t)r * F + col0 + wn + (lane & 3) * 2;
#pragma unroll
                for (int nj = 0; nj < 4; nj++) {
                    float g0 = acc[0][mi][nj][half * 2 + 0];
                    float g1 = acc[0][mi][nj][half * 2 + 1];
                    float u0 = acc[1][mi][nj][half * 2 + 0];
                    float u1 = acc[1][mi][nj][half * 2 + 1];
                    float h0 = g0 / (1.f + __expf(-g0)) * u0;
                    float h1 = g1 / (1.f + __expf(-g1)) * u1;
                    unsigned hh, hl;
                    split2(h0, h1, hh, hl);
                    *reinterpret_cast<unsigned*>(g_hh + base + nj * 8) = hh;
                    *reinterpret_cast<unsigned*>(g_hl + base + nj * 8) = hl;
                }
            }
        }
}

// ---------------------------------------------------------------------------
// cp.async stage issue for gemm2: A linear rows from g_hh/g_hl, B = Wd hi/lo.
__device__ __forceinline__ void issue2(int k0, unsigned buf, int row0, int cnt,
                                       const __nv_bfloat16* __restrict__ wdh,
                                       const __nv_bfloat16* __restrict__ wdl,
                                       int col0, int tid) {
#pragma unroll
    for (int i = 0; i < 2; i++) {
        int g = tid + i * 256;
        int r = g >> 2, q = g & 3;
        int gr = row0 + r;
        int sz = (gr < cnt) ? 16 : 0;
        size_t soff = (size_t)(gr < cnt ? gr : 0) * F + k0 + q * 8;
        unsigned da = buf + r * (APITCH * 2) + q * 16;
        cpasync16(da,           g_hh + soff, sz);
        cpasync16(da + A_BYTES, g_hl + soff, sz);
    }
    {
        int r = tid >> 3, q = tid & 7;
        size_t soff = (size_t)(k0 + r) * H + col0 + q * 8;
        unsigned db = buf + 2 * A_BYTES + r * (BPITCH * 2) + q * 16;
        cpasync16(db,           wdh + soff, 16);
        cpasync16(db + B_BYTES, wdl + soff, 16);
    }
}

// GEMM2: out[tok,:] += w * (h @ Wd). Scatter epilogue.
__global__ __launch_bounds__(256, 1) void gemm2_tc(float* __restrict__ out, int e) {
    int cnt = g_cnt[e];
    int row0 = blockIdx.y * BM;
    if (row0 >= cnt) return;
    int col0 = blockIdx.x * BN;

    const __nv_bfloat16* wdh = g_wdh + (size_t)e * F * H;
    const __nv_bfloat16* wdl = g_wdl + (size_t)e * F * H;

    extern __shared__ char smem[];
    unsigned sbase = sptr(smem);

    int tid = threadIdx.x;
    int lane = tid & 31, wid = tid >> 5;
    int wm = (wid & 3) * 32, wn = (wid >> 2) * 32;

    float acc[2][4][4];
#pragma unroll
    for (int b = 0; b < 2; b++)
#pragma unroll
        for (int c = 0; c < 4; c++)
#pragma unroll
            for (int d = 0; d < 4; d++) acc[b][c][d] = 0.f;

    const int NK = F / BK;
#pragma unroll
    for (int s = 0; s < NSTAGE - 1; s++) {
        issue2(s * BK, sbase + s * STAGE2, row0, cnt, wdh, wdl, col0, tid);
        cpcommit();
    }
    cpwait1();
    __syncthreads();

    for (int kt = 0; kt < NK; kt++) {
        int kn = kt + NSTAGE - 1;
        if (kn < NK)
            issue2(kn * BK, sbase + (kn % NSTAGE) * STAGE2, row0, cnt, wdh, wdl, col0, tid);
        cpcommit();

        unsigned sb = sbase + (kt % NSTAGE) * STAGE2;
#pragma unroll
        for (int ks = 0; ks < 2; ks++) {
            unsigned ah[2][4], al[2][4];
            int ar = wm + (lane & 15);
            int ac = ks * 16 + (lane >> 4) * 8;
#pragma unroll
            for (int mi = 0; mi < 2; mi++) {
                unsigned aoff = ((ar + mi * 16) * APITCH + ac) * 2;
                ldsm4(ah[mi], sb + aoff);
                ldsm4(al[mi], sb + A_BYTES + aoff);
            }
            int br = ks * 16 + (lane & 15), bc = wn + (lane >> 4) * 8;
            unsigned bbase = sb + 2 * A_BYTES;
            unsigned bh[2][4], bl[2][4];
#pragma unroll
            for (int nh = 0; nh < 2; nh++) {
                unsigned boff = (br * BPITCH + bc + nh * 16) * 2;
                ldsm4t(bh[nh], bbase + boff);
                ldsm4t(bl[nh], bbase + B_BYTES + boff);
            }
#pragma unroll
            for (int mi = 0; mi < 2; mi++)
#pragma unroll
                for (int nh = 0; nh < 2; nh++)
#pragma unroll
                    for (int s = 0; s < 2; s++) {
                        int nj = nh * 2 + s;
                        mma16816(acc[mi][nj], ah[mi], &bh[nh][s * 2]);
                        mma16816(acc[mi][nj], ah[mi], &bl[nh][s * 2]);
                        mma16816(acc[mi][nj], al[mi], &bh[nh][s * 2]);
                    }
        }
        cpwait1();
        __syncthreads();
    }

    // epilogue: scatter-accumulate (experts serialized by stream order)
#pragma unroll
    for (int mi = 0; mi < 2; mi++)
#pragma unroll
        for (int half = 0; half < 2; half++) {
            int m = wm + mi * 16 + (lane >> 2) + half * 8;
            int r = row0 + m;
            if (r < cnt) {
                int tok = g_idx[e][r];
                float w = g_cw[e][r];
                float* o = out + (size_t)tok * H + col0 + wn + (lane & 3) * 2;
#pragma unroll
                for (int nj = 0; nj < 4; nj++) {
                    o[nj * 8 + 0] += w * acc[mi][nj][half * 2 + 0];
                    o[nj * 8 + 1] += w * acc[mi][nj][half * 2 + 1];
                }
            }
        }
}

// ---------------------------------------------------------------------------
__global__ void finalize_kernel(float* __restrict__ out, int out_size) {
    if (threadIdx.x == 0 && blockIdx.x == 0) {
        float bal = 0.f;
#pragma unroll
        for (int e = 0; e < E; e++)
            bal += ((float)g_cnt[e] / (float)(T * TK)) * (g_sumprob[e] / (float)T);
        out[out_size - 2] = (float)E * bal;
        out[out_size - 1] = g_zsum / (float)T;
    }
}

// ---------------------------------------------------------------------------
extern "C" void kernel_launch(void* const* d_in, const int* in_sizes, int n_in,
                              void* d_out, int out_size) {
    const float* x  = (const float*)d_in[0];   // [4,2048,1024]
    const float* gw = (const float*)d_in[1];   // [1024,8]
    const float* wg = (const float*)d_in[2];   // [8,1024,4096]
    const float* wu = (const float*)d_in[3];   // [8,1024,4096]
    const float* wd = (const float*)d_in[4];   // [8,4096,1024]
    float* out = (float*)d_out;

    cudaFuncSetAttribute(gemm1_tc, cudaFuncAttributeMaxDynamicSharedMemorySize, SMEM1);
    cudaFuncSetAttribute(gemm2_tc, cudaFuncAttributeMaxDynamicSharedMemorySize, SMEM2);

    zero_kernel<<<512, 256>>>(out);

    size_t nw = (size_t)E * H * F / 4;
    convert_kernel<<<2048, 256>>>((const float4*)wg, nw, 0);
    convert_kernel<<<2048, 256>>>((const float4*)wu, nw, 1);
    convert_kernel<<<2048, 256>>>((const float4*)wd, nw, 2);
    convert_kernel<<<1024, 256>>>((const float4*)x, (size_t)T * H / 4, 3);

    router_kernel<<<T / 8, 256>>>(x, gw);

    dim3 g1(F / BN, T / BM);   // 64 x 64
    dim3 g2(H / BN, T / BM);   // 16 x 64
    for (int e = 0; e < E; e++) {
        gemm1_tc<<<g1, 256, SMEM1>>>(e);
        gemm2_tc<<<g2, 256, SMEM2>>>(out, e);
    }

    finalize_kernel<<<1, 32>>>(out, out_size);
}

// round 9
// speedup vs baseline: 1.2739x; 1.0937x over previous
#include <cuda_runtime.h>
#include <cuda_bf16.h>
#include <stdint.h>
#include <math.h>

#define H 1024
#define F 4096
#define E 8
#define TK 2
#define T 8192

#define BM 128
#define BN 64
#define BK 32
#define NSTAGE 3

#define APITCH 40
#define BPITCH 72
#define A_BYTES (BM * APITCH * 2)
#define B_BYTES (BK * BPITCH * 2)
#define STAGE1  (2 * A_BYTES + 4 * B_BYTES)
#define STAGE2  (2 * A_BYTES + 2 * B_BYTES)
#define SMEM1   (NSTAGE * STAGE1 + 512)
#define SMEM2   (NSTAGE * STAGE2)

__device__ int   g_cnt[E];
__device__ int   g_idx[E][T];
__device__ float g_cw[E][T];
__device__ float g_sumprob[E];
__device__ float g_zsum;

__device__ __align__(16) __nv_bfloat16 g_xh[(size_t)T * H];
__device__ __align__(16) __nv_bfloat16 g_xl[(size_t)T * H];
__device__ __align__(16) __nv_bfloat16 g_wgh[(size_t)E * H * F];
__device__ __align__(16) __nv_bfloat16 g_wgl[(size_t)E * H * F];
__device__ __align__(16) __nv_bfloat16 g_wuh[(size_t)E * H * F];
__device__ __align__(16) __nv_bfloat16 g_wul[(size_t)E * H * F];
__device__ __align__(16) __nv_bfloat16 g_wdh[(size_t)E * F * H];
__device__ __align__(16) __nv_bfloat16 g_wdl[(size_t)E * F * H];
// per-expert regions: expert e owns rows [e*T, e*T+cnt[e])
__device__ __align__(16) __nv_bfloat16 g_hh[(size_t)E * T * F];
__device__ __align__(16) __nv_bfloat16 g_hl[(size_t)E * T * F];

__device__ __forceinline__ unsigned sptr(const void* p) {
    return (unsigned)__cvta_generic_to_shared(p);
}
__device__ __forceinline__ void ldsm4(unsigned* r, unsigned a) {
    asm volatile("ldmatrix.sync.aligned.m8n8.x4.shared.b16 {%0,%1,%2,%3}, [%4];"
                 : "=r"(r[0]), "=r"(r[1]), "=r"(r[2]), "=r"(r[3]) : "r"(a));
}
__device__ __forceinline__ void ldsm4t(unsigned* r, unsigned a) {
    asm volatile("ldmatrix.sync.aligned.m8n8.x4.trans.shared.b16 {%0,%1,%2,%3}, [%4];"
                 : "=r"(r[0]), "=r"(r[1]), "=r"(r[2]), "=r"(r[3]) : "r"(a));
}
__device__ __forceinline__ void mma16816(float* d, const unsigned* a, const unsigned* b) {
    asm volatile("mma.sync.aligned.m16n8k16.row.col.f32.bf16.bf16.f32 "
                 "{%0,%1,%2,%3},{%4,%5,%6,%7},{%8,%9},{%0,%1,%2,%3};"
                 : "+f"(d[0]), "+f"(d[1]), "+f"(d[2]), "+f"(d[3])
                 : "r"(a[0]), "r"(a[1]), "r"(a[2]), "r"(a[3]), "r"(b[0]), "r"(b[1]));
}
__device__ __forceinline__ void split2(float x, float y, unsigned& hi, unsigned& lo) {
    __nv_bfloat16 hx = __float2bfloat16(x);
    __nv_bfloat16 hy = __float2bfloat16(y);
    __nv_bfloat16 lx = __float2bfloat16(x - __bfloat162float(hx));
    __nv_bfloat16 ly = __float2bfloat16(y - __bfloat162float(hy));
    __nv_bfloat162 h = __halves2bfloat162(hx, hy);
    __nv_bfloat162 l = __halves2bfloat162(lx, ly);
    hi = *reinterpret_cast<unsigned*>(&h);
    lo = *reinterpret_cast<unsigned*>(&l);
}
__device__ __forceinline__ void cpasync16(unsigned dst, const void* src, int sz) {
    asm volatile("cp.async.cg.shared.global [%0], [%1], 16, %2;\n"
                 :: "r"(dst), "l"(src), "r"(sz));
}
__device__ __forceinline__ void cpcommit() { asm volatile("cp.async.commit_group;\n"); }
__device__ __forceinline__ void cpwait1()  { asm volatile("cp.async.wait_group 1;\n"); }

__global__ void convert_kernel(const float4* __restrict__ src, size_t n4, int which) {
    uint2* dh; uint2* dl;
    if (which == 0)      { dh = (uint2*)g_wgh; dl = (uint2*)g_wgl; }
    else if (which == 1) { dh = (uint2*)g_wuh; dl = (uint2*)g_wul; }
    else if (which == 2) { dh = (uint2*)g_wdh; dl = (uint2*)g_wdl; }
    else                 { dh = (uint2*)g_xh;  dl = (uint2*)g_xl;  }
    size_t stride = (size_t)gridDim.x * blockDim.x;
    for (size_t i = (size_t)blockIdx.x * blockDim.x + threadIdx.x; i < n4; i += stride) {
        float4 v = src[i];
        unsigned h0, l0, h1, l1;
        split2(v.x, v.y, h0, l0);
        split2(v.z, v.w, h1, l1);
        dh[i] = make_uint2(h0, h1);
        dl[i] = make_uint2(l0, l1);
    }
}

__global__ void zero_kernel(float* __restrict__ out) {
    size_t n = (size_t)T * H;
    size_t stride = (size_t)gridDim.x * blockDim.x;
    for (size_t i = (size_t)blockIdx.x * blockDim.x + threadIdx.x; i < n; i += stride)
        out[i] = 0.f;
    if (blockIdx.x == 0 && threadIdx.x < E) {
        g_cnt[threadIdx.x] = 0;
        g_sumprob[threadIdx.x] = 0.f;
    }
    if (blockIdx.x == 0 && threadIdx.x == E) g_zsum = 0.f;
}

__global__ void router_kernel(const float* __restrict__ x,
                              const float* __restrict__ gw) {
    int warp = threadIdx.x >> 5;
    int lane = threadIdx.x & 31;
    int t = blockIdx.x * (blockDim.x >> 5) + warp;
    if (t >= T) return;

    const float* xr = x + (size_t)t * H;
    float acc[E];
#pragma unroll
    for (int e = 0; e < E; e++) acc[e] = 0.f;

    for (int h = lane; h < H; h += 32) {
        float xv = xr[h];
#pragma unroll
        for (int e = 0; e < E; e++) acc[e] += xv * gw[h * E + e];
    }
#pragma unroll
    for (int off = 16; off; off >>= 1) {
#pragma unroll
        for (int e = 0; e < E; e++)
            acc[e] += __shfl_down_sync(0xffffffffu, acc[e], off);
    }

    if (lane == 0) {
        float m = acc[0];
#pragma unroll
        for (int e = 1; e < E; e++) m = fmaxf(m, acc[e]);
        float p[E], s = 0.f;
#pragma unroll
        for (int e = 0; e < E; e++) { p[e] = __expf(acc[e] - m); s += p[e]; }
        float inv = 1.f / s;
        float lse = m + logf(s);
        atomicAdd(&g_zsum, lse * lse);

        int i1 = 0; float p1 = -1.f;
#pragma unroll
        for (int e = 0; e < E; e++) {
            float pe = p[e] * inv;
            p[e] = pe;
            atomicAdd(&g_sumprob[e], pe);
            if (pe > p1) { p1 = pe; i1 = e; }
        }
        int i2 = -1; float p2 = -1.f;
#pragma unroll
        for (int e = 0; e < E; e++) {
            if (e != i1 && p[e] > p2) { p2 = p[e]; i2 = e; }
        }
        float rs = 1.f / (p1 + p2);
        float w1 = p1 * rs, w2 = p2 * rs;

        int pos1 = atomicAdd(&g_cnt[i1], 1);
        g_idx[i1][pos1] = t; g_cw[i1][pos1] = w1;
        int pos2 = atomicAdd(&g_cnt[i2], 1);
        g_idx[i2][pos2] = t; g_cw[i2][pos2] = w2;
    }
}

__device__ __forceinline__ void issue1(int k0, unsigned buf, const int* __restrict__ ridx,
                                       const __nv_bfloat16* __restrict__ wgh,
                                       const __nv_bfloat16* __restrict__ wgl,
                                       const __nv_bfloat16* __restrict__ wuh,
                                       const __nv_bfloat16* __restrict__ wul,
                                       int col0, int tid) {
#pragma unroll
    for (int i = 0; i < 2; i++) {
        int g = tid + i * 256;
        int r = g >> 2, q = g & 3;
        int gr = ridx[r];
        int sz = (gr >= 0) ? 16 : 0;
        size_t soff = (size_t)(gr >= 0 ? gr : 0) * H + k0 + q * 8;
        unsigned da = buf + r * (APITCH * 2) + q * 16;
        cpasync16(da,           g_xh + soff, sz);
        cpasync16(da + A_BYTES, g_xl + soff, sz);
    }
    {
        int r = tid >> 3, q = tid & 7;
        size_t soff = (size_t)(k0 + r) * F + col0 + q * 8;
        unsigned db = buf + 2 * A_BYTES + r * (BPITCH * 2) + q * 16;
        cpasync16(db,               wgh + soff, 16);
        cpasync16(db + B_BYTES,     wgl + soff, 16);
        cpasync16(db + 2 * B_BYTES, wuh + soff, 16);
        cpasync16(db + 3 * B_BYTES, wul + soff, 16);
    }
}

__global__ __launch_bounds__(256, 1) void gemm1_tc() {
    int e = blockIdx.z;
    int cnt = g_cnt[e];
    int row0 = blockIdx.y * BM;
    if (row0 >= cnt) return;
    int col0 = blockIdx.x * BN;

    const __nv_bfloat16* wgh = g_wgh + (size_t)e * H * F;
    const __nv_bfloat16* wgl = g_wgl + (size_t)e * H * F;
    const __nv_bfloat16* wuh = g_wuh + (size_t)e * H * F;
    const __nv_bfloat16* wul = g_wul + (size_t)e * H * F;

    extern __shared__ char smem[];
    unsigned sbase = sptr(smem);
    int* ridx = (int*)(smem + NSTAGE * STAGE1);

    int tid = threadIdx.x;
    int lane = tid & 31, wid = tid >> 5;
    int wm = (wid & 3) * 32, wn = (wid >> 2) * 32;

    if (tid < BM) { int r = row0 + tid; ridx[tid] = (r < cnt) ? g_idx[e][r] : -1; }
    __syncthreads();

    float acc[2][2][4][4];
#pragma unroll
    for (int a = 0; a < 2; a++)
#pragma unroll
        for (int b = 0; b < 2; b++)
#pragma unroll
            for (int c = 0; c < 4; c++)
#pragma unroll
                for (int d = 0; d < 4; d++) acc[a][b][c][d] = 0.f;

    const int NK = H / BK;
#pragma unroll
    for (int s = 0; s < NSTAGE - 1; s++) {
        issue1(s * BK, sbase + s * STAGE1, ridx, wgh, wgl, wuh, wul, col0, tid);
        cpcommit();
    }
    cpwait1();
    __syncthreads();

    for (int kt = 0; kt < NK; kt++) {
        int kn = kt + NSTAGE - 1;
        if (kn < NK)
            issue1(kn * BK, sbase + (kn % NSTAGE) * STAGE1, ridx, wgh, wgl, wuh, wul, col0, tid);
        cpcommit();

        unsigned sb = sbase + (kt % NSTAGE) * STAGE1;
#pragma unroll
        for (int ks = 0; ks < 2; ks++) {
            unsigned ah[2][4], al[2][4];
            int ar = wm + (lane & 15);
            int ac = ks * 16 + (lane >> 4) * 8;
#pragma unroll
            for (int mi = 0; mi < 2; mi++) {
                unsigned aoff = ((ar + mi * 16) * APITCH + ac) * 2;
                ldsm4(ah[mi], sb + aoff);
                ldsm4(al[mi], sb + A_BYTES + aoff);
            }
            int br = ks * 16 + (lane & 15), bc = wn + (lane >> 4) * 8;
#pragma unroll
            for (int mat = 0; mat < 2; mat++) {
                unsigned bbase = sb + 2 * A_BYTES + mat * 2 * B_BYTES;
                unsigned bh[2][4], bl[2][4];
#pragma unroll
                for (int nh = 0; nh < 2; nh++) {
                    unsigned boff = (br * BPITCH + bc + nh * 16) * 2;
                    ldsm4t(bh[nh], bbase + boff);
                    ldsm4t(bl[nh], bbase + B_BYTES + boff);
                }
#pragma unroll
                for (int mi = 0; mi < 2; mi++)
#pragma unroll
                    for (int nh = 0; nh < 2; nh++)
#pragma unroll
                        for (int s = 0; s < 2; s++) {
                            int nj = nh * 2 + s;
                            mma16816(acc[mat][mi][nj], ah[mi], &bh[nh][s * 2]);
                            mma16816(acc[mat][mi][nj], ah[mi], &bl[nh][s * 2]);
                            mma16816(acc[mat][mi][nj], al[mi], &bh[nh][s * 2]);
                        }
            }
        }
        cpwait1();
        __syncthreads();
    }

#pragma unroll
    for (int mi = 0; mi < 2; mi++)
#pragma unroll
        for (int half = 0; half < 2; half++) {
            int m = wm + mi * 16 + (lane >> 2) + half * 8;
            int r = row0 + m;
            if (r < cnt) {
                size_t base = ((size_t)e * T + r) * F + col0 + wn + (lane & 3) * 2;
#pragma unroll
                for (int nj = 0; nj < 4; nj++) {
                    float g0 = acc[0][mi][nj][half * 2 + 0];
                    float g1 = acc[0][mi][nj][half * 2 + 1];
                    float u0 = acc[1][mi][nj][half * 2 + 0];
                    float u1 = acc[1][mi][nj][half * 2 + 1];
                    float h0 = g0 / (1.f + __expf(-g0)) * u0;
                    float h1 = g1 / (1.f + __expf(-g1)) * u1;
                    unsigned hh, hl;
                    split2(h0, h1, hh, hl);
                    *reinterpret_cast<unsigned*>(g_hh + base + nj * 8) = hh;
                    *reinterpret_cast<unsigned*>(g_hl + base + nj * 8) = hl;
                }
            }
        }
}

__device__ __forceinline__ void issue2(int k0, unsigned buf, size_t arow0, int rows,
                                       const __nv_bfloat16* __restrict__ wdh,
                                       const __nv_bfloat16* __restrict__ wdl,
                                       int col0, int tid) {
#pragma unroll
    for (int i = 0; i < 2; i++) {
        int g = tid + i * 256;
        int r = g >> 2, q = g & 3;
        int sz = (r < rows) ? 16 : 0;
        size_t soff = (arow0 + (r < rows ? r : 0)) * F + k0 + q * 8;
        unsigned da = buf + r * (APITCH * 2) + q * 16;
        cpasync16(da,           g_hh + soff, sz);
        cpasync16(da + A_BYTES, g_hl + soff, sz);
    }
    {
        int r = tid >> 3, q = tid & 7;
        size_t soff = (size_t)(k0 + r) * H + col0 + q * 8;
        unsigned db = buf + 2 * A_BYTES + r * (BPITCH * 2) + q * 16;
        cpasync16(db,           wdh + soff, 16);
        cpasync16(db + B_BYTES, wdl + soff, 16);
    }
}

__global__ __launch_bounds__(256, 1) void gemm2_tc(float* __restrict__ out) {
    int e = blockIdx.z;
    int cnt = g_cnt[e];
    int row0 = blockIdx.y * BM;
    if (row0 >= cnt) return;
    int col0 = blockIdx.x * BN;
    int rows = cnt - row0; if (rows > BM) rows = BM;
    size_t arow0 = (size_t)e * T + row0;

    const __nv_bfloat16* wdh = g_wdh + (size_t)e * F * H;
    const __nv_bfloat16* wdl = g_wdl + (size_t)e * F * H;

    extern __shared__ char smem[];
    unsigned sbase = sptr(smem);

    int tid = threadIdx.x;
    int lane = tid & 31, wid = tid >> 5;
    int wm = (wid & 3) * 32, wn = (wid >> 2) * 32;

    float acc[2][4][4];
#pragma unroll
    for (int b = 0; b < 2; b++)
#pragma unroll
        for (int c = 0; c < 4; c++)
#pragma unroll
            for (int d = 0; d < 4; d++) acc[b][c][d] = 0.f;

    const int NK = F / BK;
#pragma unroll
    for (int s = 0; s < NSTAGE - 1; s++) {
        issue2(s * BK, sbase + s * STAGE2, arow0, rows, wdh, wdl, col0, tid);
        cpcommit();
    }
    cpwait1();
    __syncthreads();

    for (int kt = 0; kt < NK; kt++) {
        int kn = kt + NSTAGE - 1;
        if (kn < NK)
            issue2(kn * BK, sbase + (kn % NSTAGE) * STAGE2, arow0, rows, wdh, wdl, col0, tid);
        cpcommit();

        unsigned sb = sbase + (kt % NSTAGE) * STAGE2;
#pragma unroll
        for (int ks = 0; ks < 2; ks++) {
            unsigned ah[2][4], al[2][4];
            int ar = wm + (lane & 15);
            int ac = ks * 16 + (lane >> 4) * 8;
#pragma unroll
            for (int mi = 0; mi < 2; mi++) {
                unsigned aoff = ((ar + mi * 16) * APITCH + ac) * 2;
                ldsm4(ah[mi], sb + aoff);
                ldsm4(al[mi], sb + A_BYTES + aoff);
            }
            int br = ks * 16 + (lane & 15), bc = wn + (lane >> 4) * 8;
            unsigned bbase = sb + 2 * A_BYTES;
            unsigned bh[2][4], bl[2][4];
#pragma unroll
            for (int nh = 0; nh < 2; nh++) {
                unsigned boff = (br * BPITCH + bc + nh * 16) * 2;
                ldsm4t(bh[nh], bbase + boff);
                ldsm4t(bl[nh], bbase + B_BYTES + boff);
            }
#pragma unroll
            for (int mi = 0; mi < 2; mi++)
#pragma unroll
                for (int nh = 0; nh < 2; nh++)
#pragma unroll
                    for (int s = 0; s < 2; s++) {
                        int nj = nh * 2 + s;
                        mma16816(acc[mi][nj], ah[mi], &bh[nh][s * 2]);
                        mma16816(acc[mi][nj], ah[mi], &bl[nh][s * 2]);
                        mma16816(acc[mi][nj], al[mi], &bh[nh][s * 2]);
                    }
        }
        cpwait1();
        __syncthreads();
    }

#pragma unroll
    for (int mi = 0; mi < 2; mi++)
#pragma unroll
        for (int half = 0; half < 2; half++) {
            int m = wm + mi * 16 + (lane >> 2) + half * 8;
            int r = row0 + m;
            if (r < cnt) {
                int tok = g_idx[e][r];
                float w = g_cw[e][r];
                float* o = out + (size_t)tok * H + col0 + wn + (lane & 3) * 2;
#pragma unroll
                for (int nj = 0; nj < 4; nj++) {
                    atomicAdd(&o[nj * 8 + 0], w * acc[mi][nj][half * 2 + 0]);
                    atomicAdd(&o[nj * 8 + 1], w * acc[mi][nj][half * 2 + 1]);
                }
            }
        }
}

__global__ void finalize_kernel(float* __restrict__ out, int out_size) {
    if (threadIdx.x == 0 && blockIdx.x == 0) {
        float bal = 0.f;
#pragma unroll
        for (int e = 0; e < E; e++)
            bal += ((float)g_cnt[e] / (float)(T * TK)) * (g_sumprob[e] / (float)T);
        out[out_size - 2] = (float)E * bal;
        out[out_size - 1] = g_zsum / (float)T;
    }
}

extern "C" void kernel_launch(void* const* d_in, const int* in_sizes, int n_in,
                              void* d_out, int out_size) {
    const float* x  = (const float*)d_in[0];
    const float* gw = (const float*)d_in[1];
    const float* wg = (const float*)d_in[2];
    const float* wu = (const float*)d_in[3];
    const float* wd = (const float*)d_in[4];
    float* out = (float*)d_out;

    cudaFuncSetAttribute(gemm1_tc, cudaFuncAttributeMaxDynamicSharedMemorySize, SMEM1);
    cudaFuncSetAttribute(gemm2_tc, cudaFuncAttributeMaxDynamicSharedMemorySize, SMEM2);

    zero_kernel<<<512, 256>>>(out);

    size_t nw = (size_t)E * H * F / 4;
    convert_kernel<<<2048, 256>>>((const float4*)wg, nw, 0);
    convert_kernel<<<2048, 256>>>((const float4*)wu, nw, 1);
    convert_kernel<<<2048, 256>>>((const float4*)wd, nw, 2);
    convert_kernel<<<1024, 256>>>((const float4*)x, (size_t)T * H / 4, 3);

    router_kernel<<<T / 8, 256>>>(x, gw);

    dim3 g1(F / BN, T / BM, E);   // 64 x 64 x 8, inactive tiles exit fast
    dim3 g2(H / BN, T / BM, E);   // 16 x 64 x 8
    gemm1_tc<<<g1, 256, SMEM1>>>();
    gemm2_tc<<<g2, 256, SMEM2>>>(out);

    finalize_kernel<<<1, 32>>>(out, out_size);
}